// round 10
// baseline (speedup 1.0000x reference)
#include <cuda_runtime.h>
#include <cuda_fp16.h>
#include <math.h>
#include <stdint.h>

#define B_  4
#define S_  2048
#define D_  768
#define H_  12
#define HD_ 64
#define N3_ (3*D_)
#define M_  (B_*S_)

// Scratch (allocation-free rule: __device__ globals)
__device__ __half g_q[B_*H_*S_*HD_];    // [b,h,s,d] fp16
__device__ __half g_k[B_*H_*S_*HD_];    // [b,h,s,d] fp16
__device__ __half g_v[B_*H_*HD_*S_];    // [b,h,d,s] fp16  (TRANSPOSED)
__device__ __half g_attn[M_*D_];        // [b,s, h*64+d] fp16
__device__ __half g_x[M_*D_];           // fp16 x
__device__ __half g_wq[N3_*D_];         // w_qkv^T  [N3][K] fp16
__device__ __half g_wp[D_*D_];          // w_proj^T [N][K]  fp16

// ---------------------------------------------------------------------------
// helpers
// ---------------------------------------------------------------------------
__device__ __forceinline__ void mma16(float c[4], const uint32_t a[4], const uint32_t b[2]) {
    asm("mma.sync.aligned.m16n8k16.row.col.f32.f16.f16.f32 "
        "{%0,%1,%2,%3},{%4,%5,%6,%7},{%8,%9},{%0,%1,%2,%3};"
        : "+f"(c[0]), "+f"(c[1]), "+f"(c[2]), "+f"(c[3])
        : "r"(a[0]), "r"(a[1]), "r"(a[2]), "r"(a[3]), "r"(b[0]), "r"(b[1]));
}
__device__ __forceinline__ void ldsm4(uint32_t r[4], uint32_t addr) {
    asm volatile("ldmatrix.sync.aligned.m8n8.x4.shared.b16 {%0,%1,%2,%3}, [%4];"
        : "=r"(r[0]), "=r"(r[1]), "=r"(r[2]), "=r"(r[3]) : "r"(addr));
}
__device__ __forceinline__ void cp16(uint32_t sdst, const void* gsrc) {
    asm volatile("cp.async.cg.shared.global [%0], [%1], 16;" :: "r"(sdst), "l"(gsrc));
}
__device__ __forceinline__ void cp_commit() {
    asm volatile("cp.async.commit_group;" ::: "memory");
}
__device__ __forceinline__ uint32_t s2u(const void* p) {
    return (uint32_t)__cvta_generic_to_shared(p);
}
__device__ __forceinline__ uint32_t h2bits(__half2 h) {
    return *reinterpret_cast<uint32_t*>(&h);
}

// ---------------------------------------------------------------------------
// pre-round: x -> fp16 ; weights -> transposed [N][K] fp16
// ---------------------------------------------------------------------------
__global__ void pre_round_x(const float* __restrict__ x)
{
    const float4* src = (const float4*)x;
    __half2* dst = (__half2*)g_x;
    int n4 = (M_*D_)/4;
    for (int i = blockIdx.x * blockDim.x + threadIdx.x; i < n4;
         i += gridDim.x * blockDim.x) {
        float4 v = src[i];
        dst[i*2]   = __floats2half2_rn(v.x, v.y);
        dst[i*2+1] = __floats2half2_rn(v.z, v.w);
    }
}

__global__ void transpose_round(const float* __restrict__ src, int cols, int which)
{
    __shared__ float t[32][33];
    __half* dst = which ? g_wp : g_wq;   // [cols][768]
    int c0 = blockIdx.x * 32, r0 = blockIdx.y * 32;
    int x = threadIdx.x, y = threadIdx.y;   // 32 x 8
    #pragma unroll
    for (int i = y; i < 32; i += 8)
        t[i][x] = src[(size_t)(r0 + i) * cols + c0 + x];
    __syncthreads();
    #pragma unroll
    for (int i = y; i < 32; i += 8)
        dst[(size_t)(c0 + i) * D_ + r0 + x] = __float2half_rn(t[x][i]);
}

// ---------------------------------------------------------------------------
// fp16 GEMM, cp.async 2-stage + ldmatrix, k-tile 64:
// C = A[M,768] @ Wt[N,768]^T + bias. CTA 128x128, 256 threads, 8 warps (4x2).
// ---------------------------------------------------------------------------
#define GAP 72
#define GA_HALFS (128*GAP)
#define GSTG_HALFS (2*GA_HALFS)

template<bool QKV>
__global__ __launch_bounds__(256, 2) void gemm_h(
    const float* __restrict__ bias, float* __restrict__ C)
{
    extern __shared__ __half hsm[];
    const int K = D_;
    int tid = threadIdx.x, bx = blockIdx.x, by = blockIdx.y;
    int lane = tid & 31, wid = tid >> 5, lg = lane >> 2, lq = lane & 3;
    int wm = (wid >> 1) * 32, wn = (wid & 1) * 64;

    const __half* Ab = QKV ? (const __half*)g_x  : (const __half*)g_attn;
    const __half* Bt = QKV ? (const __half*)g_wq : (const __half*)g_wp;

    int r = tid >> 1, p = tid & 1;                  // p: 32-half segment of row
    const __half* asrc = Ab + (size_t)(by * 128 + r) * K + p * 32;
    const __half* bsrc = Bt + (size_t)(bx * 128 + r) * K + p * 32;
    uint32_t a_s = s2u(hsm) + (r * GAP + p * 32) * 2;
    uint32_t b_s = s2u(hsm) + (GA_HALFS + r * GAP + p * 32) * 2;

    // ldmatrix lane offsets (bytes, relative to stage base)
    uint32_t offA[2], offB[4];
    {
        int arow = (lane & 15), acol = (lane >> 4) << 3;
        #pragma unroll
        for (int mt = 0; mt < 2; mt++)
            offA[mt] = ((wm + mt * 16 + arow) * GAP + acol) * 2;
        int brow = ((lane >> 4) << 3) + (lane & 7);
        int bcol = ((lane >> 3) & 1) << 3;
        #pragma unroll
        for (int ntp = 0; ntp < 4; ntp++)
            offB[ntp] = (uint32_t)(GA_HALFS + (wn + ntp * 16 + brow) * GAP + bcol) * 2;
    }

    float acc[2][8][4];
    #pragma unroll
    for (int mt = 0; mt < 2; mt++)
        #pragma unroll
        for (int nt = 0; nt < 8; nt++)
            #pragma unroll
            for (int i = 0; i < 4; i++) acc[mt][nt][i] = 0.f;

    #define GLOAD(ch, st) do {                                   \
        uint32_t ao = a_s + (st) * (GSTG_HALFS * 2);              \
        uint32_t bo = b_s + (st) * (GSTG_HALFS * 2);              \
        const __half* ap = asrc + (ch) * 64;                      \
        const __half* bp = bsrc + (ch) * 64;                      \
        cp16(ao,      ap);      cp16(ao + 16, ap + 8);            \
        cp16(ao + 32, ap + 16); cp16(ao + 48, ap + 24);           \
        cp16(bo,      bp);      cp16(bo + 16, bp + 8);            \
        cp16(bo + 32, bp + 16); cp16(bo + 48, bp + 24);           \
        cp_commit();                                              \
    } while (0)

    GLOAD(0, 0);

    for (int it = 0; it < 12; it++) {
        if (it < 11) {
            GLOAD(it + 1, (it + 1) & 1);
            asm volatile("cp.async.wait_group 1;" ::: "memory");
        } else {
            asm volatile("cp.async.wait_group 0;" ::: "memory");
        }
        __syncthreads();

        uint32_t sb = s2u(hsm) + (it & 1) * (GSTG_HALFS * 2);

        #pragma unroll
        for (int ks = 0; ks < 4; ks++) {
            uint32_t kadd = ks * 32;   // 16 halves
            uint32_t af[2][4], bf[8][2];
            #pragma unroll
            for (int mt = 0; mt < 2; mt++)
                ldsm4(af[mt], sb + offA[mt] + kadd);
            #pragma unroll
            for (int ntp = 0; ntp < 4; ntp++) {
                uint32_t t[4];
                ldsm4(t, sb + offB[ntp] + kadd);
                bf[2*ntp][0] = t[0]; bf[2*ntp][1] = t[1];
                bf[2*ntp+1][0] = t[2]; bf[2*ntp+1][1] = t[3];
            }
            #pragma unroll
            for (int mt = 0; mt < 2; mt++)
                #pragma unroll
                for (int nt = 0; nt < 8; nt++)
                    mma16(acc[mt][nt], af[mt], bf[nt]);
        }
        __syncthreads();
    }

    // Epilogue
    #pragma unroll
    for (int mt = 0; mt < 2; mt++) {
        #pragma unroll
        for (int rp = 0; rp < 2; rp++) {
            int m = by * 128 + wm + mt * 16 + lg + rp * 8;
            if (QKV) {
                int bb = m >> 11;
                int ss = m & (S_ - 1);
                #pragma unroll
                for (int nt = 0; nt < 8; nt++) {
                    int n = bx * 128 + wn + nt * 8 + 2 * lq;
                    int which = n / D_;
                    int rem = n - which * D_;
                    int hh = rem >> 6, dd = rem & 63;
                    float vx = acc[mt][nt][rp*2 + 0] + bias[n];
                    float vy = acc[mt][nt][rp*2 + 1] + bias[n + 1];
                    if (which == 2) {
                        size_t vi = ((size_t)(bb * H_ + hh) * HD_ + dd) * S_ + ss;
                        g_v[vi]      = __float2half_rn(vx);
                        g_v[vi + S_] = __float2half_rn(vy);
                    } else {
                        __half* dst = (which == 0) ? g_q : g_k;
                        size_t idx = (((size_t)(bb * H_ + hh) * S_ + ss) << 6) + dd;
                        *(__half2*)&dst[idx] = __floats2half2_rn(vx, vy);
                    }
                }
            } else {
                #pragma unroll
                for (int nt = 0; nt < 8; nt++) {
                    int n = bx * 128 + wn + nt * 8 + 2 * lq;
                    float2 v;
                    v.x = acc[mt][nt][rp*2 + 0] + bias[n];
                    v.y = acc[mt][nt][rp*2 + 1] + bias[n + 1];
                    *(float2*)&C[(size_t)m * D_ + n] = v;
                }
            }
        }
    }
}

// ---------------------------------------------------------------------------
// Flash attention, causal, all-fp16 mma, ldmatrix K/V, register P.
// One block = (b, h, 128-row q tile); 256 threads (8 warps, 16 rows each).
// K/V 64-wide tiles shared by all 8 warps. SMEM: Ks[64][72]h, Vs[64][72]h.
// ---------------------------------------------------------------------------
#define KSP 72
#define ATILE (64*KSP)

__global__ __launch_bounds__(256) void flash_attn_h()
{
    extern __shared__ __half hsm[];
    __half* Ks = hsm;
    __half* Vs = hsm + ATILE;

    int bid = blockIdx.x;
    int t  = 15 - (bid & 15);          // heavy q-tiles first
    int h  = (bid >> 4) % H_;
    int b  = bid / (16 * H_);
    int tid = threadIdx.x;
    int lane = tid & 31, w = tid >> 5, lg = lane >> 2, lq = lane & 3;
    int q0 = t * 128;
    int diag = 2 * t + (w >> 2);       // this warp's diagonal k-tile
    int nkt  = 2 * t + 2;              // k-tiles for this block

    const __half* Qg = g_q + (size_t)(b * H_ + h) * S_ * HD_;
    const __half* Kg = g_k + (size_t)(b * H_ + h) * S_ * HD_;
    const __half* Vg = g_v + (size_t)(b * H_ + h) * HD_ * S_;   // [d][s]

    // load mapping: 256 threads, 64 rows, 4 threads/row, 16 halves each
    int r_ = tid >> 2, seg = tid & 3;
    uint32_t ks_u = s2u(Ks) + (r_ * KSP + seg * 16) * 2;
    uint32_t vs_u = s2u(Vs) + (r_ * KSP + seg * 16) * 2;
    const __half* kg_row = Kg + (size_t)r_ * 64 + seg * 16;
    const __half* vg_row = Vg + (size_t)r_ * S_ + seg * 16;

    // ldmatrix lane offsets for K/V B-fragments
    uint32_t offK[4], offV[4];
    {
        int brow = ((lane >> 4) << 3) + (lane & 7);
        int bcol = ((lane >> 3) & 1) << 3;
        #pragma unroll
        for (int ntp = 0; ntp < 4; ntp++) {
            offK[ntp] = s2u(Ks) + ((ntp * 16 + brow) * KSP + bcol) * 2;
            offV[ntp] = s2u(Vs) + ((ntp * 16 + brow) * KSP + bcol) * 2;
        }
    }

    // Q fragments straight from global, scaled by 0.125 (exact in fp16)
    const __half2 sc2 = __floats2half2_rn(0.125f, 0.125f);
    uint32_t qf[4][4];
    {
        const __half* qr0 = Qg + (size_t)(q0 + w*16 + lg    ) * 64;
        const __half* qr1 = Qg + (size_t)(q0 + w*16 + lg + 8) * 64;
        #pragma unroll
        for (int ks = 0; ks < 4; ks++) {
            int kc = ks * 16 + 2 * lq;
            __half2 h0 = __hmul2(*(const __half2*)(qr0 + kc),     sc2);
            __half2 h1 = __hmul2(*(const __half2*)(qr1 + kc),     sc2);
            __half2 h2 = __hmul2(*(const __half2*)(qr0 + kc + 8), sc2);
            __half2 h3 = __hmul2(*(const __half2*)(qr1 + kc + 8), sc2);
            qf[ks][0] = h2bits(h0); qf[ks][1] = h2bits(h1);
            qf[ks][2] = h2bits(h2); qf[ks][3] = h2bits(h3);
        }
    }

    float mrow[2] = {-INFINITY, -INFINITY};
    float lrow[2] = {0.f, 0.f};
    float o[8][4];
    #pragma unroll
    for (int nt = 0; nt < 8; nt++)
        #pragma unroll
        for (int i = 0; i < 4; i++) o[nt][i] = 0.f;

    for (int kt = 0; kt < nkt; kt++) {
        __syncthreads();   // prior LDSM reads of Ks/Vs done
        {
            const __half* kp = kg_row + (size_t)kt * 64 * 64;
            const __half* vp = vg_row + (size_t)kt * 64;
            cp16(ks_u,      kp);     cp16(ks_u + 16, kp + 8);
            cp16(vs_u,      vp);     cp16(vs_u + 16, vp + 8);
            cp_commit();
        }
        asm volatile("cp.async.wait_group 0;" ::: "memory");
        __syncthreads();

        if (kt > diag) continue;   // warps 0-3 skip the final k-tile

        // S = (Q*scale) @ K^T
        float s[8][4];
        #pragma unroll
        for (int nt = 0; nt < 8; nt++)
            #pragma unroll
            for (int i = 0; i < 4; i++) s[nt][i] = 0.f;

        #pragma unroll
        for (int ks = 0; ks < 4; ks++) {
            uint32_t kadd = ks * 32;
            uint32_t bv[8][2];
            #pragma unroll
            for (int ntp = 0; ntp < 4; ntp++) {
                uint32_t tt[4];
                ldsm4(tt, offK[ntp] + kadd);
                bv[2*ntp][0] = tt[0]; bv[2*ntp][1] = tt[1];
                bv[2*ntp+1][0] = tt[2]; bv[2*ntp+1][1] = tt[3];
            }
            #pragma unroll
            for (int nt = 0; nt < 8; nt++)
                mma16(s[nt], qf[ks], bv[nt]);
        }

        if (kt == diag) {   // diagonal tile: causal mask (local row uses w&3)
            #pragma unroll
            for (int nt = 0; nt < 8; nt++)
                #pragma unroll
                for (int rp = 0; rp < 2; rp++)
                    #pragma unroll
                    for (int j = 0; j < 2; j++) {
                        int col = nt*8 + 2*lq + j;
                        int row = (w & 3)*16 + lg + rp*8;
                        if (col > row) s[nt][rp*2 + j] = -INFINITY;
                    }
        }

        // Online softmax (thread owns rows lg, lg+8 of its warp tile)
        #pragma unroll
        for (int rp = 0; rp < 2; rp++) {
            float mt = -INFINITY;
            #pragma unroll
            for (int nt = 0; nt < 8; nt++)
                mt = fmaxf(mt, fmaxf(s[nt][rp*2], s[nt][rp*2 + 1]));
            mt = fmaxf(mt, __shfl_xor_sync(0xffffffffu, mt, 1));
            mt = fmaxf(mt, __shfl_xor_sync(0xffffffffu, mt, 2));
            float mnew = fmaxf(mrow[rp], mt);
            float alpha = __expf(mrow[rp] - mnew);
            float rs = 0.f;
            #pragma unroll
            for (int nt = 0; nt < 8; nt++) {
                float e0 = __expf(s[nt][rp*2]     - mnew);
                float e1 = __expf(s[nt][rp*2 + 1] - mnew);
                s[nt][rp*2] = e0; s[nt][rp*2 + 1] = e1;
                rs += e0 + e1;
            }
            rs += __shfl_xor_sync(0xffffffffu, rs, 1);
            rs += __shfl_xor_sync(0xffffffffu, rs, 2);
            lrow[rp] = lrow[rp] * alpha + rs;
            mrow[rp] = mnew;
            #pragma unroll
            for (int nt = 0; nt < 8; nt++) {
                o[nt][rp*2]     *= alpha;
                o[nt][rp*2 + 1] *= alpha;
            }
        }

        // O += P @ V : P's C-fragment reinterpreted as A-fragment in registers
        #pragma unroll
        for (int ks = 0; ks < 4; ks++) {
            uint32_t pa[4];
            pa[0] = h2bits(__floats2half2_rn(s[2*ks][0],   s[2*ks][1]));
            pa[1] = h2bits(__floats2half2_rn(s[2*ks][2],   s[2*ks][3]));
            pa[2] = h2bits(__floats2half2_rn(s[2*ks+1][0], s[2*ks+1][1]));
            pa[3] = h2bits(__floats2half2_rn(s[2*ks+1][2], s[2*ks+1][3]));
            uint32_t kadd = ks * 32;
            uint32_t bv[8][2];
            #pragma unroll
            for (int ntp = 0; ntp < 4; ntp++) {
                uint32_t tt[4];
                ldsm4(tt, offV[ntp] + kadd);
                bv[2*ntp][0] = tt[0]; bv[2*ntp][1] = tt[1];
                bv[2*ntp+1][0] = tt[2]; bv[2*ntp+1][1] = tt[3];
            }
            #pragma unroll
            for (int nt = 0; nt < 8; nt++)
                mma16(o[nt], pa, bv[nt]);
        }
    }

    // Normalize, fp16-round (proj A operand), write [b, s, h*64+d]
    #pragma unroll
    for (int rp = 0; rp < 2; rp++) {
        float inv = 1.f / lrow[rp];
        int row = q0 + w*16 + lg + rp*8;
        #pragma unroll
        for (int nt = 0; nt < 8; nt++) {
            int d = nt*8 + 2*lq;
            __half2 hv = __floats2half2_rn(o[nt][rp*2] * inv, o[nt][rp*2 + 1] * inv);
            *(__half2*)&g_attn[((size_t)(b * S_ + row)) * D_ + h * 64 + d] = hv;
        }
    }
}

// ---------------------------------------------------------------------------
extern "C" void kernel_launch(void* const* d_in, const int* in_sizes, int n_in,
                              void* d_out, int out_size)
{
    const float* x      = (const float*)d_in[0];
    const float* w_qkv  = (const float*)d_in[1];
    const float* b_qkv  = (const float*)d_in[2];
    const float* w_proj = (const float*)d_in[3];
    const float* b_proj = (const float*)d_in[4];
    float* out = (float*)d_out;

    pre_round_x<<<512, 256>>>(x);
    transpose_round<<<dim3(N3_/32, D_/32), dim3(32, 8)>>>(w_qkv, N3_, 0);
    transpose_round<<<dim3(D_/32,  D_/32), dim3(32, 8)>>>(w_proj, D_, 1);

    int gsmem = 2 * GSTG_HALFS * (int)sizeof(__half);   // 73728 B
    cudaFuncSetAttribute(gemm_h<true>,
                         cudaFuncAttributeMaxDynamicSharedMemorySize, gsmem);
    cudaFuncSetAttribute(gemm_h<false>,
                         cudaFuncAttributeMaxDynamicSharedMemorySize, gsmem);

    dim3 g1(N3_/128, M_/128);   // (18, 64)
    gemm_h<true><<<g1, 256, gsmem>>>(b_qkv, nullptr);

    int asmem = 2 * ATILE * (int)sizeof(__half);        // 18432 B
    cudaFuncSetAttribute(flash_attn_h,
                         cudaFuncAttributeMaxDynamicSharedMemorySize, asmem);
    flash_attn_h<<<B_ * H_ * (S_/128), 256, asmem>>>();

    dim3 g2(D_/128, M_/128);    // (6, 64)
    gemm_h<false><<<g2, 256, gsmem>>>(b_proj, out);
}

// round 11
// speedup vs baseline: 1.0724x; 1.0724x over previous
#include <cuda_runtime.h>
#include <cuda_fp16.h>
#include <math.h>
#include <stdint.h>

#define B_  4
#define S_  2048
#define D_  768
#define H_  12
#define HD_ 64
#define N3_ (3*D_)
#define M_  (B_*S_)

// Scratch (allocation-free rule: __device__ globals)
__device__ __half g_q[B_*H_*S_*HD_];    // [b,h,s,d] fp16
__device__ __half g_k[B_*H_*S_*HD_];    // [b,h,s,d] fp16
__device__ __half g_v[B_*H_*HD_*S_];    // [b,h,d,s] fp16  (TRANSPOSED)
__device__ __half g_attn[M_*D_];        // [b,s, h*64+d] fp16
__device__ __half g_x[M_*D_];           // fp16 x
__device__ __half g_wq[N3_*D_];         // w_qkv^T  [N3][K] fp16
__device__ __half g_wp[D_*D_];          // w_proj^T [N][K]  fp16

// ---------------------------------------------------------------------------
// helpers
// ---------------------------------------------------------------------------
__device__ __forceinline__ void mma16(float c[4], const uint32_t a[4], const uint32_t b[2]) {
    asm("mma.sync.aligned.m16n8k16.row.col.f32.f16.f16.f32 "
        "{%0,%1,%2,%3},{%4,%5,%6,%7},{%8,%9},{%0,%1,%2,%3};"
        : "+f"(c[0]), "+f"(c[1]), "+f"(c[2]), "+f"(c[3])
        : "r"(a[0]), "r"(a[1]), "r"(a[2]), "r"(a[3]), "r"(b[0]), "r"(b[1]));
}
__device__ __forceinline__ void ldsm4(uint32_t r[4], uint32_t addr) {
    asm volatile("ldmatrix.sync.aligned.m8n8.x4.shared.b16 {%0,%1,%2,%3}, [%4];"
        : "=r"(r[0]), "=r"(r[1]), "=r"(r[2]), "=r"(r[3]) : "r"(addr));
}
__device__ __forceinline__ void cp16(uint32_t sdst, const void* gsrc) {
    asm volatile("cp.async.cg.shared.global [%0], [%1], 16;" :: "r"(sdst), "l"(gsrc));
}
__device__ __forceinline__ void cp_commit() {
    asm volatile("cp.async.commit_group;" ::: "memory");
}
__device__ __forceinline__ uint32_t s2u(const void* p) {
    return (uint32_t)__cvta_generic_to_shared(p);
}
__device__ __forceinline__ uint32_t h2bits(__half2 h) {
    return *reinterpret_cast<uint32_t*>(&h);
}

// ---------------------------------------------------------------------------
// pre-round: x -> fp16 ; weights -> transposed [N][K] fp16
// ---------------------------------------------------------------------------
__global__ void pre_round_x(const float* __restrict__ x)
{
    const float4* src = (const float4*)x;
    __half2* dst = (__half2*)g_x;
    int n4 = (M_*D_)/4;
    for (int i = blockIdx.x * blockDim.x + threadIdx.x; i < n4;
         i += gridDim.x * blockDim.x) {
        float4 v = src[i];
        dst[i*2]   = __floats2half2_rn(v.x, v.y);
        dst[i*2+1] = __floats2half2_rn(v.z, v.w);
    }
}

__global__ void transpose_round(const float* __restrict__ src, int cols, int which)
{
    __shared__ float t[32][33];
    __half* dst = which ? g_wp : g_wq;   // [cols][768]
    int c0 = blockIdx.x * 32, r0 = blockIdx.y * 32;
    int x = threadIdx.x, y = threadIdx.y;   // 32 x 8
    #pragma unroll
    for (int i = y; i < 32; i += 8)
        t[i][x] = src[(size_t)(r0 + i) * cols + c0 + x];
    __syncthreads();
    #pragma unroll
    for (int i = y; i < 32; i += 8)
        dst[(size_t)(c0 + i) * D_ + r0 + x] = __float2half_rn(t[x][i]);
}

// ---------------------------------------------------------------------------
// fp16 GEMM (round-9 best: k-tile 32), cp.async 2-stage + ldmatrix:
// C = A[M,768] @ Wt[N,768]^T + bias. CTA 128x128, 256 threads, 8 warps (4x2).
// ---------------------------------------------------------------------------
#define GAP 40
#define GA_HALFS (128*GAP)
#define GSTG_HALFS (2*GA_HALFS)

template<bool QKV>
__global__ __launch_bounds__(256, 2) void gemm_h(
    const float* __restrict__ bias, float* __restrict__ C)
{
    extern __shared__ __half hsm[];
    const int K = D_;
    int tid = threadIdx.x, bx = blockIdx.x, by = blockIdx.y;
    int lane = tid & 31, wid = tid >> 5, lg = lane >> 2, lq = lane & 3;
    int wm = (wid >> 1) * 32, wn = (wid & 1) * 64;

    const __half* Ab = QKV ? (const __half*)g_x  : (const __half*)g_attn;
    const __half* Bt = QKV ? (const __half*)g_wq : (const __half*)g_wp;

    int r = tid >> 1, p = tid & 1;
    const __half* asrc = Ab + (size_t)(by * 128 + r) * K + p * 16;
    const __half* bsrc = Bt + (size_t)(bx * 128 + r) * K + p * 16;
    uint32_t a_s = s2u(hsm) + (r * GAP + p * 16) * 2;
    uint32_t b_s = s2u(hsm) + (GA_HALFS + r * GAP + p * 16) * 2;

    // ldmatrix lane offsets (bytes, relative to stage base)
    uint32_t offA[2], offB[4];
    {
        int arow = (lane & 15), acol = (lane >> 4) << 3;
        #pragma unroll
        for (int mt = 0; mt < 2; mt++)
            offA[mt] = ((wm + mt * 16 + arow) * GAP + acol) * 2;
        int brow = ((lane >> 4) << 3) + (lane & 7);
        int bcol = ((lane >> 3) & 1) << 3;
        #pragma unroll
        for (int ntp = 0; ntp < 4; ntp++)
            offB[ntp] = (uint32_t)(GA_HALFS + (wn + ntp * 16 + brow) * GAP + bcol) * 2;
    }

    float acc[2][8][4];
    #pragma unroll
    for (int mt = 0; mt < 2; mt++)
        #pragma unroll
        for (int nt = 0; nt < 8; nt++)
            #pragma unroll
            for (int i = 0; i < 4; i++) acc[mt][nt][i] = 0.f;

    #define GLOAD(ch, st) do {                                  \
        uint32_t ao = a_s + (st) * (GSTG_HALFS * 2);            \
        uint32_t bo = b_s + (st) * (GSTG_HALFS * 2);            \
        const __half* ap = asrc + (ch) * 32;                    \
        const __half* bp = bsrc + (ch) * 32;                    \
        cp16(ao,      ap);     cp16(ao + 16, ap + 8);           \
        cp16(bo,      bp);     cp16(bo + 16, bp + 8);           \
        cp_commit();                                            \
    } while (0)

    GLOAD(0, 0);

    for (int it = 0; it < 24; it++) {
        if (it < 23) {
            GLOAD(it + 1, (it + 1) & 1);
            asm volatile("cp.async.wait_group 1;" ::: "memory");
        } else {
            asm volatile("cp.async.wait_group 0;" ::: "memory");
        }
        __syncthreads();

        uint32_t sb = s2u(hsm) + (it & 1) * (GSTG_HALFS * 2);

        #pragma unroll
        for (int ks = 0; ks < 2; ks++) {
            uint32_t kadd = ks * 32;   // 16 halves
            uint32_t af[2][4], bf[8][2];
            #pragma unroll
            for (int mt = 0; mt < 2; mt++)
                ldsm4(af[mt], sb + offA[mt] + kadd);
            #pragma unroll
            for (int ntp = 0; ntp < 4; ntp++) {
                uint32_t t[4];
                ldsm4(t, sb + offB[ntp] + kadd);
                bf[2*ntp][0] = t[0]; bf[2*ntp][1] = t[1];
                bf[2*ntp+1][0] = t[2]; bf[2*ntp+1][1] = t[3];
            }
            #pragma unroll
            for (int mt = 0; mt < 2; mt++)
                #pragma unroll
                for (int nt = 0; nt < 8; nt++)
                    mma16(acc[mt][nt], af[mt], bf[nt]);
        }
        __syncthreads();
    }

    // Epilogue
    #pragma unroll
    for (int mt = 0; mt < 2; mt++) {
        #pragma unroll
        for (int rp = 0; rp < 2; rp++) {
            int m = by * 128 + wm + mt * 16 + lg + rp * 8;
            if (QKV) {
                int bb = m >> 11;
                int ss = m & (S_ - 1);
                #pragma unroll
                for (int nt = 0; nt < 8; nt++) {
                    int n = bx * 128 + wn + nt * 8 + 2 * lq;
                    int which = n / D_;
                    int rem = n - which * D_;
                    int hh = rem >> 6, dd = rem & 63;
                    float vx = acc[mt][nt][rp*2 + 0] + bias[n];
                    float vy = acc[mt][nt][rp*2 + 1] + bias[n + 1];
                    if (which == 2) {
                        size_t vi = ((size_t)(bb * H_ + hh) * HD_ + dd) * S_ + ss;
                        g_v[vi]      = __float2half_rn(vx);
                        g_v[vi + S_] = __float2half_rn(vy);
                    } else {
                        __half* dst = (which == 0) ? g_q : g_k;
                        size_t idx = (((size_t)(bb * H_ + hh) * S_ + ss) << 6) + dd;
                        *(__half2*)&dst[idx] = __floats2half2_rn(vx, vy);
                    }
                }
            } else {
                #pragma unroll
                for (int nt = 0; nt < 8; nt++) {
                    int n = bx * 128 + wn + nt * 8 + 2 * lq;
                    float2 v;
                    v.x = acc[mt][nt][rp*2 + 0] + bias[n];
                    v.y = acc[mt][nt][rp*2 + 1] + bias[n + 1];
                    *(float2*)&C[(size_t)m * D_ + n] = v;
                }
            }
        }
    }
}

// ---------------------------------------------------------------------------
// Flash attention (round-10 best), causal, all-fp16 mma, ldmatrix K/V,
// register P. One block = (b, h, 128-row q tile); 256 threads (8 warps).
// K/V 64-wide tiles shared by all 8 warps. SMEM: Ks[64][72]h, Vs[64][72]h.
// ---------------------------------------------------------------------------
#define KSP 72
#define ATILE (64*KSP)

__global__ __launch_bounds__(256) void flash_attn_h()
{
    extern __shared__ __half hsm[];
    __half* Ks = hsm;
    __half* Vs = hsm + ATILE;

    int bid = blockIdx.x;
    int t  = 15 - (bid & 15);          // heavy q-tiles first
    int h  = (bid >> 4) % H_;
    int b  = bid / (16 * H_);
    int tid = threadIdx.x;
    int lane = tid & 31, w = tid >> 5, lg = lane >> 2, lq = lane & 3;
    int q0 = t * 128;
    int diag = 2 * t + (w >> 2);       // this warp's diagonal k-tile
    int nkt  = 2 * t + 2;              // k-tiles for this block

    const __half* Qg = g_q + (size_t)(b * H_ + h) * S_ * HD_;
    const __half* Kg = g_k + (size_t)(b * H_ + h) * S_ * HD_;
    const __half* Vg = g_v + (size_t)(b * H_ + h) * HD_ * S_;   // [d][s]

    // load mapping: 256 threads, 64 rows, 4 threads/row, 16 halves each
    int r_ = tid >> 2, seg = tid & 3;
    uint32_t ks_u = s2u(Ks) + (r_ * KSP + seg * 16) * 2;
    uint32_t vs_u = s2u(Vs) + (r_ * KSP + seg * 16) * 2;
    const __half* kg_row = Kg + (size_t)r_ * 64 + seg * 16;
    const __half* vg_row = Vg + (size_t)r_ * S_ + seg * 16;

    // ldmatrix lane offsets for K/V B-fragments
    uint32_t offK[4], offV[4];
    {
        int brow = ((lane >> 4) << 3) + (lane & 7);
        int bcol = ((lane >> 3) & 1) << 3;
        #pragma unroll
        for (int ntp = 0; ntp < 4; ntp++) {
            offK[ntp] = s2u(Ks) + ((ntp * 16 + brow) * KSP + bcol) * 2;
            offV[ntp] = s2u(Vs) + ((ntp * 16 + brow) * KSP + bcol) * 2;
        }
    }

    // Q fragments straight from global, scaled by 0.125 (exact in fp16)
    const __half2 sc2 = __floats2half2_rn(0.125f, 0.125f);
    uint32_t qf[4][4];
    {
        const __half* qr0 = Qg + (size_t)(q0 + w*16 + lg    ) * 64;
        const __half* qr1 = Qg + (size_t)(q0 + w*16 + lg + 8) * 64;
        #pragma unroll
        for (int ks = 0; ks < 4; ks++) {
            int kc = ks * 16 + 2 * lq;
            __half2 h0 = __hmul2(*(const __half2*)(qr0 + kc),     sc2);
            __half2 h1 = __hmul2(*(const __half2*)(qr1 + kc),     sc2);
            __half2 h2 = __hmul2(*(const __half2*)(qr0 + kc + 8), sc2);
            __half2 h3 = __hmul2(*(const __half2*)(qr1 + kc + 8), sc2);
            qf[ks][0] = h2bits(h0); qf[ks][1] = h2bits(h1);
            qf[ks][2] = h2bits(h2); qf[ks][3] = h2bits(h3);
        }
    }

    float mrow[2] = {-INFINITY, -INFINITY};
    float lrow[2] = {0.f, 0.f};
    float o[8][4];
    #pragma unroll
    for (int nt = 0; nt < 8; nt++)
        #pragma unroll
        for (int i = 0; i < 4; i++) o[nt][i] = 0.f;

    for (int kt = 0; kt < nkt; kt++) {
        __syncthreads();   // prior LDSM reads of Ks/Vs done
        {
            const __half* kp = kg_row + (size_t)kt * 64 * 64;
            const __half* vp = vg_row + (size_t)kt * 64;
            cp16(ks_u,      kp);     cp16(ks_u + 16, kp + 8);
            cp16(vs_u,      vp);     cp16(vs_u + 16, vp + 8);
            cp_commit();
        }
        asm volatile("cp.async.wait_group 0;" ::: "memory");
        __syncthreads();

        if (kt > diag) continue;   // warps 0-3 skip the final k-tile

        // S = (Q*scale) @ K^T
        float s[8][4];
        #pragma unroll
        for (int nt = 0; nt < 8; nt++)
            #pragma unroll
            for (int i = 0; i < 4; i++) s[nt][i] = 0.f;

        #pragma unroll
        for (int ks = 0; ks < 4; ks++) {
            uint32_t kadd = ks * 32;
            uint32_t bv[8][2];
            #pragma unroll
            for (int ntp = 0; ntp < 4; ntp++) {
                uint32_t tt[4];
                ldsm4(tt, offK[ntp] + kadd);
                bv[2*ntp][0] = tt[0]; bv[2*ntp][1] = tt[1];
                bv[2*ntp+1][0] = tt[2]; bv[2*ntp+1][1] = tt[3];
            }
            #pragma unroll
            for (int nt = 0; nt < 8; nt++)
                mma16(s[nt], qf[ks], bv[nt]);
        }

        if (kt == diag) {   // diagonal tile: causal mask (local row uses w&3)
            #pragma unroll
            for (int nt = 0; nt < 8; nt++)
                #pragma unroll
                for (int rp = 0; rp < 2; rp++)
                    #pragma unroll
                    for (int j = 0; j < 2; j++) {
                        int col = nt*8 + 2*lq + j;
                        int row = (w & 3)*16 + lg + rp*8;
                        if (col > row) s[nt][rp*2 + j] = -INFINITY;
                    }
        }

        // Online softmax (thread owns rows lg, lg+8 of its warp tile)
        #pragma unroll
        for (int rp = 0; rp < 2; rp++) {
            float mt = -INFINITY;
            #pragma unroll
            for (int nt = 0; nt < 8; nt++)
                mt = fmaxf(mt, fmaxf(s[nt][rp*2], s[nt][rp*2 + 1]));
            mt = fmaxf(mt, __shfl_xor_sync(0xffffffffu, mt, 1));
            mt = fmaxf(mt, __shfl_xor_sync(0xffffffffu, mt, 2));
            float mnew = fmaxf(mrow[rp], mt);
            float alpha = __expf(mrow[rp] - mnew);
            float rs = 0.f;
            #pragma unroll
            for (int nt = 0; nt < 8; nt++) {
                float e0 = __expf(s[nt][rp*2]     - mnew);
                float e1 = __expf(s[nt][rp*2 + 1] - mnew);
                s[nt][rp*2] = e0; s[nt][rp*2 + 1] = e1;
                rs += e0 + e1;
            }
            rs += __shfl_xor_sync(0xffffffffu, rs, 1);
            rs += __shfl_xor_sync(0xffffffffu, rs, 2);
            lrow[rp] = lrow[rp] * alpha + rs;
            mrow[rp] = mnew;
            #pragma unroll
            for (int nt = 0; nt < 8; nt++) {
                o[nt][rp*2]     *= alpha;
                o[nt][rp*2 + 1] *= alpha;
            }
        }

        // O += P @ V : P's C-fragment reinterpreted as A-fragment in registers
        #pragma unroll
        for (int ks = 0; ks < 4; ks++) {
            uint32_t pa[4];
            pa[0] = h2bits(__floats2half2_rn(s[2*ks][0],   s[2*ks][1]));
            pa[1] = h2bits(__floats2half2_rn(s[2*ks][2],   s[2*ks][3]));
            pa[2] = h2bits(__floats2half2_rn(s[2*ks+1][0], s[2*ks+1][1]));
            pa[3] = h2bits(__floats2half2_rn(s[2*ks+1][2], s[2*ks+1][3]));
            uint32_t kadd = ks * 32;
            uint32_t bv[8][2];
            #pragma unroll
            for (int ntp = 0; ntp < 4; ntp++) {
                uint32_t tt[4];
                ldsm4(tt, offV[ntp] + kadd);
                bv[2*ntp][0] = tt[0]; bv[2*ntp][1] = tt[1];
                bv[2*ntp+1][0] = tt[2]; bv[2*ntp+1][1] = tt[3];
            }
            #pragma unroll
            for (int nt = 0; nt < 8; nt++)
                mma16(o[nt], pa, bv[nt]);
        }
    }

    // Normalize, fp16-round (proj A operand), write [b, s, h*64+d]
    #pragma unroll
    for (int rp = 0; rp < 2; rp++) {
        float inv = 1.f / lrow[rp];
        int row = q0 + w*16 + lg + rp*8;
        #pragma unroll
        for (int nt = 0; nt < 8; nt++) {
            int d = nt*8 + 2*lq;
            __half2 hv = __floats2half2_rn(o[nt][rp*2] * inv, o[nt][rp*2 + 1] * inv);
            *(__half2*)&g_attn[((size_t)(b * S_ + row)) * D_ + h * 64 + d] = hv;
        }
    }
}

// ---------------------------------------------------------------------------
extern "C" void kernel_launch(void* const* d_in, const int* in_sizes, int n_in,
                              void* d_out, int out_size)
{
    const float* x      = (const float*)d_in[0];
    const float* w_qkv  = (const float*)d_in[1];
    const float* b_qkv  = (const float*)d_in[2];
    const float* w_proj = (const float*)d_in[3];
    const float* b_proj = (const float*)d_in[4];
    float* out = (float*)d_out;

    pre_round_x<<<512, 256>>>(x);
    transpose_round<<<dim3(N3_/32, D_/32), dim3(32, 8)>>>(w_qkv, N3_, 0);
    transpose_round<<<dim3(D_/32,  D_/32), dim3(32, 8)>>>(w_proj, D_, 1);

    int gsmem = 2 * GSTG_HALFS * (int)sizeof(__half);   // 40960 B
    cudaFuncSetAttribute(gemm_h<true>,
                         cudaFuncAttributeMaxDynamicSharedMemorySize, gsmem);
    cudaFuncSetAttribute(gemm_h<false>,
                         cudaFuncAttributeMaxDynamicSharedMemorySize, gsmem);

    dim3 g1(N3_/128, M_/128);   // (18, 64)
    gemm_h<true><<<g1, 256, gsmem>>>(b_qkv, nullptr);

    int asmem = 2 * ATILE * (int)sizeof(__half);        // 18432 B
    cudaFuncSetAttribute(flash_attn_h,
                         cudaFuncAttributeMaxDynamicSharedMemorySize, asmem);
    flash_attn_h<<<B_ * H_ * (S_/128), 256, asmem>>>();

    dim3 g2(D_/128, M_/128);    // (6, 64)
    gemm_h<false><<<g2, 256, gsmem>>>(b_proj, out);
}

// round 12
// speedup vs baseline: 1.1086x; 1.0337x over previous
#include <cuda_runtime.h>
#include <cuda_fp16.h>
#include <math.h>
#include <stdint.h>

#define B_  4
#define S_  2048
#define D_  768
#define H_  12
#define HD_ 64
#define N3_ (3*D_)
#define M_  (B_*S_)

// Scratch (allocation-free rule: __device__ globals)
__device__ __half g_q[B_*H_*S_*HD_];    // [b,h,s,d] fp16
__device__ __half g_k[B_*H_*S_*HD_];    // [b,h,s,d] fp16
__device__ __half g_v[B_*H_*HD_*S_];    // [b,h,d,s] fp16  (TRANSPOSED)
__device__ __half g_attn[M_*D_];        // [b,s, h*64+d] fp16
__device__ __half g_x[M_*D_];           // fp16 x
__device__ __half g_wq[N3_*D_];         // w_qkv^T  [N3][K] fp16
__device__ __half g_wp[D_*D_];          // w_proj^T [N][K]  fp16

// ---------------------------------------------------------------------------
// helpers
// ---------------------------------------------------------------------------
__device__ __forceinline__ void mma16(float c[4], const uint32_t a[4], const uint32_t b[2]) {
    asm("mma.sync.aligned.m16n8k16.row.col.f32.f16.f16.f32 "
        "{%0,%1,%2,%3},{%4,%5,%6,%7},{%8,%9},{%0,%1,%2,%3};"
        : "+f"(c[0]), "+f"(c[1]), "+f"(c[2]), "+f"(c[3])
        : "r"(a[0]), "r"(a[1]), "r"(a[2]), "r"(a[3]), "r"(b[0]), "r"(b[1]));
}
__device__ __forceinline__ void ldsm4(uint32_t r[4], uint32_t addr) {
    asm volatile("ldmatrix.sync.aligned.m8n8.x4.shared.b16 {%0,%1,%2,%3}, [%4];"
        : "=r"(r[0]), "=r"(r[1]), "=r"(r[2]), "=r"(r[3]) : "r"(addr));
}
__device__ __forceinline__ void cp16(uint32_t sdst, const void* gsrc) {
    asm volatile("cp.async.cg.shared.global [%0], [%1], 16;" :: "r"(sdst), "l"(gsrc));
}
__device__ __forceinline__ void cp_commit() {
    asm volatile("cp.async.commit_group;" ::: "memory");
}
__device__ __forceinline__ uint32_t s2u(const void* p) {
    return (uint32_t)__cvta_generic_to_shared(p);
}
__device__ __forceinline__ uint32_t h2bits(__half2 h) {
    return *reinterpret_cast<uint32_t*>(&h);
}

// ---------------------------------------------------------------------------
// pre-round: x -> fp16 ; weights -> transposed [N][K] fp16
// ---------------------------------------------------------------------------
__global__ void pre_round_x(const float* __restrict__ x)
{
    const float4* src = (const float4*)x;
    __half2* dst = (__half2*)g_x;
    int n4 = (M_*D_)/4;
    for (int i = blockIdx.x * blockDim.x + threadIdx.x; i < n4;
         i += gridDim.x * blockDim.x) {
        float4 v = src[i];
        dst[i*2]   = __floats2half2_rn(v.x, v.y);
        dst[i*2+1] = __floats2half2_rn(v.z, v.w);
    }
}

__global__ void transpose_round(const float* __restrict__ src, int cols, int which)
{
    __shared__ float t[32][33];
    __half* dst = which ? g_wp : g_wq;   // [cols][768]
    int c0 = blockIdx.x * 32, r0 = blockIdx.y * 32;
    int x = threadIdx.x, y = threadIdx.y;   // 32 x 8
    #pragma unroll
    for (int i = y; i < 32; i += 8)
        t[i][x] = src[(size_t)(r0 + i) * cols + c0 + x];
    __syncthreads();
    #pragma unroll
    for (int i = y; i < 32; i += 8)
        dst[(size_t)(c0 + i) * D_ + r0 + x] = __float2half_rn(t[x][i]);
}

// ---------------------------------------------------------------------------
// fp16 GEMM, 3-stage cp.async + ldmatrix, ONE sync per k-iter:
// C = A[M,768] @ Wt[N,768]^T + bias. CTA 128x128 (k-tile 32), 256 thr, 8 warps.
// ---------------------------------------------------------------------------
#define GAP 40
#define GA_HALFS (128*GAP)
#define GSTG_HALFS (2*GA_HALFS)
#define GSTG_B (GSTG_HALFS*2)

template<bool QKV>
__global__ __launch_bounds__(256, 2) void gemm_h(
    const float* __restrict__ bias, float* __restrict__ C)
{
    extern __shared__ __half hsm[];
    const int K = D_;
    int tid = threadIdx.x, bx = blockIdx.x, by = blockIdx.y;
    int lane = tid & 31, wid = tid >> 5, lg = lane >> 2, lq = lane & 3;
    int wm = (wid >> 1) * 32, wn = (wid & 1) * 64;

    const __half* Ab = QKV ? (const __half*)g_x  : (const __half*)g_attn;
    const __half* Bt = QKV ? (const __half*)g_wq : (const __half*)g_wp;

    int r = tid >> 1, p = tid & 1;
    const __half* asrc = Ab + (size_t)(by * 128 + r) * K + p * 16;
    const __half* bsrc = Bt + (size_t)(bx * 128 + r) * K + p * 16;
    uint32_t a_s = s2u(hsm) + (r * GAP + p * 16) * 2;
    uint32_t b_s = s2u(hsm) + (GA_HALFS + r * GAP + p * 16) * 2;

    // ldmatrix lane offsets (bytes, relative to stage base)
    uint32_t offA[2], offB[4];
    {
        int arow = (lane & 15), acol = (lane >> 4) << 3;
        #pragma unroll
        for (int mt = 0; mt < 2; mt++)
            offA[mt] = ((wm + mt * 16 + arow) * GAP + acol) * 2;
        int brow = ((lane >> 4) << 3) + (lane & 7);
        int bcol = ((lane >> 3) & 1) << 3;
        #pragma unroll
        for (int ntp = 0; ntp < 4; ntp++)
            offB[ntp] = (uint32_t)(GA_HALFS + (wn + ntp * 16 + brow) * GAP + bcol) * 2;
    }

    float acc[2][8][4];
    #pragma unroll
    for (int mt = 0; mt < 2; mt++)
        #pragma unroll
        for (int nt = 0; nt < 8; nt++)
            #pragma unroll
            for (int i = 0; i < 4; i++) acc[mt][nt][i] = 0.f;

    #define GLOAD(ch, st) do {                                  \
        uint32_t ao = a_s + (st) * GSTG_B;                      \
        uint32_t bo = b_s + (st) * GSTG_B;                      \
        const __half* ap = asrc + (ch) * 32;                    \
        const __half* bp = bsrc + (ch) * 32;                    \
        cp16(ao,      ap);     cp16(ao + 16, ap + 8);           \
        cp16(bo,      bp);     cp16(bo + 16, bp + 8);           \
        cp_commit();                                            \
    } while (0)

    GLOAD(0, 0);
    GLOAD(1, 1);

    for (int it = 0; it < 24; it++) {
        if (it < 23) asm volatile("cp.async.wait_group 1;" ::: "memory");
        else         asm volatile("cp.async.wait_group 0;" ::: "memory");
        __syncthreads();   // single barrier per iteration

        if (it + 2 < 24) {
            int st2 = (it + 2) % 3;
            GLOAD(it + 2, st2);   // writes stage (it-1)%3 — free since all
                                  // warps finished iter it-1 before this sync
        }

        uint32_t sb = s2u(hsm) + (it % 3) * GSTG_B;

        #pragma unroll
        for (int ks = 0; ks < 2; ks++) {
            uint32_t kadd = ks * 32;   // 16 halves
            uint32_t af[2][4], bf[8][2];
            #pragma unroll
            for (int mt = 0; mt < 2; mt++)
                ldsm4(af[mt], sb + offA[mt] + kadd);
            #pragma unroll
            for (int ntp = 0; ntp < 4; ntp++) {
                uint32_t t[4];
                ldsm4(t, sb + offB[ntp] + kadd);
                bf[2*ntp][0] = t[0]; bf[2*ntp][1] = t[1];
                bf[2*ntp+1][0] = t[2]; bf[2*ntp+1][1] = t[3];
            }
            #pragma unroll
            for (int mt = 0; mt < 2; mt++)
                #pragma unroll
                for (int nt = 0; nt < 8; nt++)
                    mma16(acc[mt][nt], af[mt], bf[nt]);
        }
    }

    // Epilogue
    #pragma unroll
    for (int mt = 0; mt < 2; mt++) {
        #pragma unroll
        for (int rp = 0; rp < 2; rp++) {
            int m = by * 128 + wm + mt * 16 + lg + rp * 8;
            if (QKV) {
                int bb = m >> 11;
                int ss = m & (S_ - 1);
                #pragma unroll
                for (int nt = 0; nt < 8; nt++) {
                    int n = bx * 128 + wn + nt * 8 + 2 * lq;
                    int which = n / D_;
                    int rem = n - which * D_;
                    int hh = rem >> 6, dd = rem & 63;
                    float vx = acc[mt][nt][rp*2 + 0] + bias[n];
                    float vy = acc[mt][nt][rp*2 + 1] + bias[n + 1];
                    if (which == 2) {
                        size_t vi = ((size_t)(bb * H_ + hh) * HD_ + dd) * S_ + ss;
                        g_v[vi]      = __float2half_rn(vx);
                        g_v[vi + S_] = __float2half_rn(vy);
                    } else {
                        __half* dst = (which == 0) ? g_q : g_k;
                        size_t idx = (((size_t)(bb * H_ + hh) * S_ + ss) << 6) + dd;
                        *(__half2*)&dst[idx] = __floats2half2_rn(vx, vy);
                    }
                }
            } else {
                #pragma unroll
                for (int nt = 0; nt < 8; nt++) {
                    int n = bx * 128 + wn + nt * 8 + 2 * lq;
                    float2 v;
                    v.x = acc[mt][nt][rp*2 + 0] + bias[n];
                    v.y = acc[mt][nt][rp*2 + 1] + bias[n + 1];
                    *(float2*)&C[(size_t)m * D_ + n] = v;
                }
            }
        }
    }
}

// ---------------------------------------------------------------------------
// Flash attention, causal, all-fp16 mma, ldmatrix K/V, register P,
// 2-stage double-buffered K/V, ONE sync per k-tile.
// One block = (b, h, 128-row q tile); 256 threads (8 warps, 16 rows each).
// SMEM: 2 stages x (Ks[64][72] + Vs[64][72]) fp16 = 36864 B.
// ---------------------------------------------------------------------------
#define KSP 72
#define ATILE (64*KSP)
#define ASTG_B (2*ATILE*2)   // K+V per stage, bytes

__global__ __launch_bounds__(256) void flash_attn_h()
{
    extern __shared__ __half hsm[];

    int bid = blockIdx.x;
    int t  = 15 - (bid & 15);          // heavy q-tiles first
    int h  = (bid >> 4) % H_;
    int b  = bid / (16 * H_);
    int tid = threadIdx.x;
    int lane = tid & 31, w = tid >> 5, lg = lane >> 2, lq = lane & 3;
    int q0 = t * 128;
    int diag = 2 * t + (w >> 2);       // this warp's diagonal k-tile
    int nkt  = 2 * t + 2;              // k-tiles for this block

    const __half* Qg = g_q + (size_t)(b * H_ + h) * S_ * HD_;
    const __half* Kg = g_k + (size_t)(b * H_ + h) * S_ * HD_;
    const __half* Vg = g_v + (size_t)(b * H_ + h) * HD_ * S_;   // [d][s]

    // load mapping: 256 threads, 64 rows, 4 threads/row, 16 halves each
    int r_ = tid >> 2, seg = tid & 3;
    uint32_t ks_u = s2u(hsm) + (r_ * KSP + seg * 16) * 2;
    uint32_t vs_u = ks_u + ATILE * 2;
    const __half* kg_row = Kg + (size_t)r_ * 64 + seg * 16;
    const __half* vg_row = Vg + (size_t)r_ * S_ + seg * 16;

    // ldmatrix lane offsets for K/V B-fragments (stage-relative)
    uint32_t offK[4], offV[4];
    {
        int brow = ((lane >> 4) << 3) + (lane & 7);
        int bcol = ((lane >> 3) & 1) << 3;
        #pragma unroll
        for (int ntp = 0; ntp < 4; ntp++) {
            offK[ntp] = s2u(hsm) + ((ntp * 16 + brow) * KSP + bcol) * 2;
            offV[ntp] = offK[ntp] + ATILE * 2;
        }
    }

    #define APRE(kt, st) do {                                        \
        uint32_t so = (st) * ASTG_B;                                 \
        const __half* kp = kg_row + (size_t)(kt) * 64 * 64;          \
        const __half* vp = vg_row + (size_t)(kt) * 64;               \
        cp16(ks_u + so,      kp);   cp16(ks_u + so + 16, kp + 8);    \
        cp16(vs_u + so,      vp);   cp16(vs_u + so + 16, vp + 8);    \
        cp_commit();                                                 \
    } while (0)

    // Q fragments straight from global, scaled by 0.125 (exact in fp16)
    APRE(0, 0);
    const __half2 sc2 = __floats2half2_rn(0.125f, 0.125f);
    uint32_t qf[4][4];
    {
        const __half* qr0 = Qg + (size_t)(q0 + w*16 + lg    ) * 64;
        const __half* qr1 = Qg + (size_t)(q0 + w*16 + lg + 8) * 64;
        #pragma unroll
        for (int ks = 0; ks < 4; ks++) {
            int kc = ks * 16 + 2 * lq;
            __half2 h0 = __hmul2(*(const __half2*)(qr0 + kc),     sc2);
            __half2 h1 = __hmul2(*(const __half2*)(qr1 + kc),     sc2);
            __half2 h2 = __hmul2(*(const __half2*)(qr0 + kc + 8), sc2);
            __half2 h3 = __hmul2(*(const __half2*)(qr1 + kc + 8), sc2);
            qf[ks][0] = h2bits(h0); qf[ks][1] = h2bits(h1);
            qf[ks][2] = h2bits(h2); qf[ks][3] = h2bits(h3);
        }
    }

    float mrow[2] = {-INFINITY, -INFINITY};
    float lrow[2] = {0.f, 0.f};
    float o[8][4];
    #pragma unroll
    for (int nt = 0; nt < 8; nt++)
        #pragma unroll
        for (int i = 0; i < 4; i++) o[nt][i] = 0.f;

    for (int kt = 0; kt < nkt; kt++) {
        int st = kt & 1;
        asm volatile("cp.async.wait_group 0;" ::: "memory");
        __syncthreads();   // single barrier per k-tile

        if (kt + 1 < nkt)
            APRE(kt + 1, st ^ 1);   // overlaps with compute below; buffer st^1
                                    // was last read at kt-1 (done before sync)

        if (kt > diag) continue;    // warps 0-3 skip the final k-tile

        uint32_t so = st * ASTG_B;

        // S = (Q*scale) @ K^T
        float s[8][4];
        #pragma unroll
        for (int nt = 0; nt < 8; nt++)
            #pragma unroll
            for (int i = 0; i < 4; i++) s[nt][i] = 0.f;

        #pragma unroll
        for (int ks = 0; ks < 4; ks++) {
            uint32_t kadd = so + ks * 32;
            uint32_t bv[8][2];
            #pragma unroll
            for (int ntp = 0; ntp < 4; ntp++) {
                uint32_t tt[4];
                ldsm4(tt, offK[ntp] + kadd);
                bv[2*ntp][0] = tt[0]; bv[2*ntp][1] = tt[1];
                bv[2*ntp+1][0] = tt[2]; bv[2*ntp+1][1] = tt[3];
            }
            #pragma unroll
            for (int nt = 0; nt < 8; nt++)
                mma16(s[nt], qf[ks], bv[nt]);
        }

        if (kt == diag) {   // diagonal tile: causal mask (local row uses w&3)
            #pragma unroll
            for (int nt = 0; nt < 8; nt++)
                #pragma unroll
                for (int rp = 0; rp < 2; rp++)
                    #pragma unroll
                    for (int j = 0; j < 2; j++) {
                        int col = nt*8 + 2*lq + j;
                        int row = (w & 3)*16 + lg + rp*8;
                        if (col > row) s[nt][rp*2 + j] = -INFINITY;
                    }
        }

        // Online softmax (thread owns rows lg, lg+8 of its warp tile)
        #pragma unroll
        for (int rp = 0; rp < 2; rp++) {
            float mt = -INFINITY;
            #pragma unroll
            for (int nt = 0; nt < 8; nt++)
                mt = fmaxf(mt, fmaxf(s[nt][rp*2], s[nt][rp*2 + 1]));
            mt = fmaxf(mt, __shfl_xor_sync(0xffffffffu, mt, 1));
            mt = fmaxf(mt, __shfl_xor_sync(0xffffffffu, mt, 2));
            float mnew = fmaxf(mrow[rp], mt);
            float alpha = __expf(mrow[rp] - mnew);
            float rs = 0.f;
            #pragma unroll
            for (int nt = 0; nt < 8; nt++) {
                float e0 = __expf(s[nt][rp*2]     - mnew);
                float e1 = __expf(s[nt][rp*2 + 1] - mnew);
                s[nt][rp*2] = e0; s[nt][rp*2 + 1] = e1;
                rs += e0 + e1;
            }
            rs += __shfl_xor_sync(0xffffffffu, rs, 1);
            rs += __shfl_xor_sync(0xffffffffu, rs, 2);
            lrow[rp] = lrow[rp] * alpha + rs;
            mrow[rp] = mnew;
            #pragma unroll
            for (int nt = 0; nt < 8; nt++) {
                o[nt][rp*2]     *= alpha;
                o[nt][rp*2 + 1] *= alpha;
            }
        }

        // O += P @ V : P's C-fragment reinterpreted as A-fragment in registers
        #pragma unroll
        for (int ks = 0; ks < 4; ks++) {
            uint32_t pa[4];
            pa[0] = h2bits(__floats2half2_rn(s[2*ks][0],   s[2*ks][1]));
            pa[1] = h2bits(__floats2half2_rn(s[2*ks][2],   s[2*ks][3]));
            pa[2] = h2bits(__floats2half2_rn(s[2*ks+1][0], s[2*ks+1][1]));
            pa[3] = h2bits(__floats2half2_rn(s[2*ks+1][2], s[2*ks+1][3]));
            uint32_t kadd = so + ks * 32;
            uint32_t bv[8][2];
            #pragma unroll
            for (int ntp = 0; ntp < 4; ntp++) {
                uint32_t tt[4];
                ldsm4(tt, offV[ntp] + kadd);
                bv[2*ntp][0] = tt[0]; bv[2*ntp][1] = tt[1];
                bv[2*ntp+1][0] = tt[2]; bv[2*ntp+1][1] = tt[3];
            }
            #pragma unroll
            for (int nt = 0; nt < 8; nt++)
                mma16(o[nt], pa, bv[nt]);
        }
    }

    // Normalize, fp16-round (proj A operand), write [b, s, h*64+d]
    #pragma unroll
    for (int rp = 0; rp < 2; rp++) {
        float inv = 1.f / lrow[rp];
        int row = q0 + w*16 + lg + rp*8;
        #pragma unroll
        for (int nt = 0; nt < 8; nt++) {
            int d = nt*8 + 2*lq;
            __half2 hv = __floats2half2_rn(o[nt][rp*2] * inv, o[nt][rp*2 + 1] * inv);
            *(__half2*)&g_attn[((size_t)(b * S_ + row)) * D_ + h * 64 + d] = hv;
        }
    }
}

// ---------------------------------------------------------------------------
extern "C" void kernel_launch(void* const* d_in, const int* in_sizes, int n_in,
                              void* d_out, int out_size)
{
    const float* x      = (const float*)d_in[0];
    const float* w_qkv  = (const float*)d_in[1];
    const float* b_qkv  = (const float*)d_in[2];
    const float* w_proj = (const float*)d_in[3];
    const float* b_proj = (const float*)d_in[4];
    float* out = (float*)d_out;

    pre_round_x<<<512, 256>>>(x);
    transpose_round<<<dim3(N3_/32, D_/32), dim3(32, 8)>>>(w_qkv, N3_, 0);
    transpose_round<<<dim3(D_/32,  D_/32), dim3(32, 8)>>>(w_proj, D_, 1);

    int gsmem = 3 * GSTG_B;   // 61440 B (3 stages)
    cudaFuncSetAttribute(gemm_h<true>,
                         cudaFuncAttributeMaxDynamicSharedMemorySize, gsmem);
    cudaFuncSetAttribute(gemm_h<false>,
                         cudaFuncAttributeMaxDynamicSharedMemorySize, gsmem);

    dim3 g1(N3_/128, M_/128);   // (18, 64)
    gemm_h<true><<<g1, 256, gsmem>>>(b_qkv, nullptr);

    int asmem = 2 * ASTG_B;     // 36864 B (2 stages)
    cudaFuncSetAttribute(flash_attn_h,
                         cudaFuncAttributeMaxDynamicSharedMemorySize, asmem);
    flash_attn_h<<<B_ * H_ * (S_/128), 256, asmem>>>();

    dim3 g2(D_/128, M_/128);    // (6, 64)
    gemm_h<false><<<g2, 256, gsmem>>>(b_proj, out);
}

// round 13
// speedup vs baseline: 1.1196x; 1.0100x over previous
#include <cuda_runtime.h>
#include <cuda_fp16.h>
#include <math.h>
#include <stdint.h>

#define B_  4
#define S_  2048
#define D_  768
#define H_  12
#define HD_ 64
#define N3_ (3*D_)
#define M_  (B_*S_)

// Scratch (allocation-free rule: __device__ globals)
__device__ __half g_q[B_*H_*S_*HD_];    // [b,h,s,d] fp16
__device__ __half g_k[B_*H_*S_*HD_];    // [b,h,s,d] fp16
__device__ __half g_v[B_*H_*HD_*S_];    // [b,h,d,s] fp16  (TRANSPOSED)
__device__ __half g_attn[M_*D_];        // [b,s, h*64+d] fp16
__device__ __half g_x[M_*D_];           // fp16 x
__device__ __half g_wq[N3_*D_];         // w_qkv^T  [N3][K] fp16
__device__ __half g_wp[D_*D_];          // w_proj^T [N][K]  fp16

// ---------------------------------------------------------------------------
// helpers
// ---------------------------------------------------------------------------
__device__ __forceinline__ void mma16(float c[4], const uint32_t a[4], const uint32_t b[2]) {
    asm("mma.sync.aligned.m16n8k16.row.col.f32.f16.f16.f32 "
        "{%0,%1,%2,%3},{%4,%5,%6,%7},{%8,%9},{%0,%1,%2,%3};"
        : "+f"(c[0]), "+f"(c[1]), "+f"(c[2]), "+f"(c[3])
        : "r"(a[0]), "r"(a[1]), "r"(a[2]), "r"(a[3]), "r"(b[0]), "r"(b[1]));
}
__device__ __forceinline__ void ldsm4(uint32_t r[4], uint32_t addr) {
    asm volatile("ldmatrix.sync.aligned.m8n8.x4.shared.b16 {%0,%1,%2,%3}, [%4];"
        : "=r"(r[0]), "=r"(r[1]), "=r"(r[2]), "=r"(r[3]) : "r"(addr));
}
__device__ __forceinline__ void cp16(uint32_t sdst, const void* gsrc) {
    asm volatile("cp.async.cg.shared.global [%0], [%1], 16;" :: "r"(sdst), "l"(gsrc));
}
__device__ __forceinline__ void cp_commit() {
    asm volatile("cp.async.commit_group;" ::: "memory");
}
__device__ __forceinline__ uint32_t s2u(const void* p) {
    return (uint32_t)__cvta_generic_to_shared(p);
}
__device__ __forceinline__ uint32_t h2bits(__half2 h) {
    return *reinterpret_cast<uint32_t*>(&h);
}

// ---------------------------------------------------------------------------
// prep (single launch): transpose+round both weights, round x to fp16
// blocks [0,1728): wq ; [1728,2304): wp ; [2304,2560): x
// ---------------------------------------------------------------------------
__global__ void prep_all(const float* __restrict__ x,
                         const float* __restrict__ wq,
                         const float* __restrict__ wp)
{
    int bx = blockIdx.x;
    if (bx < 1728 + 576) {
        __shared__ float t[32][33];
        const float* src; __half* dst; int cols, c0, r0;
        if (bx < 1728) {
            src = wq; dst = g_wq; cols = N3_;
            c0 = (bx % 72) * 32; r0 = (bx / 72) * 32;
        } else {
            int idx = bx - 1728;
            src = wp; dst = g_wp; cols = D_;
            c0 = (idx % 24) * 32; r0 = (idx / 24) * 32;
        }
        int tx = threadIdx.x & 31, ty = threadIdx.x >> 5;   // 32 x 8
        #pragma unroll
        for (int i = ty; i < 32; i += 8)
            t[i][tx] = src[(size_t)(r0 + i) * cols + c0 + tx];
        __syncthreads();
        #pragma unroll
        for (int i = ty; i < 32; i += 8)
            dst[(size_t)(c0 + i) * D_ + r0 + tx] = __float2half_rn(t[tx][i]);
    } else {
        const float4* src = (const float4*)x;
        __half2* dst = (__half2*)g_x;
        int n4 = (M_*D_)/4;
        for (int i = (bx - 2304) * blockDim.x + threadIdx.x; i < n4;
             i += 256 * blockDim.x) {
            float4 v = src[i];
            dst[i*2]   = __floats2half2_rn(v.x, v.y);
            dst[i*2+1] = __floats2half2_rn(v.z, v.w);
        }
    }
}

// ---------------------------------------------------------------------------
// fp16 GEMM, 256x128 CTA tile (k-tile 32), 512 threads, 16 warps (8x2),
// 3-stage cp.async + ldmatrix, one sync per k-iter.
// C = A[M,768] @ Wt[N,768]^T + bias.
// ---------------------------------------------------------------------------
#define GAP 40
#define GA_HALFS (256*GAP)                // A tile
#define GB_HALFS (128*GAP)                // B tile
#define GSTG_HALFS (GA_HALFS + GB_HALFS)  // 15360
#define GSTG_B (GSTG_HALFS*2)             // 30720

template<bool QKV>
__global__ __launch_bounds__(512, 1) void gemm_h(
    const float* __restrict__ bias, float* __restrict__ C)
{
    extern __shared__ __half hsm[];
    const int K = D_;
    int tid = threadIdx.x, bx = blockIdx.x, by = blockIdx.y;
    int lane = tid & 31, wid = tid >> 5, lg = lane >> 2, lq = lane & 3;
    int wm = (wid >> 1) * 32, wn = (wid & 1) * 64;

    const __half* Ab = QKV ? (const __half*)g_x  : (const __half*)g_attn;
    const __half* Bt = QKV ? (const __half*)g_wq : (const __half*)g_wp;

    int r = tid >> 1, p = tid & 1;
    const __half* asrc = Ab + (size_t)(by * 256 + r) * K + p * 16;    // 256 rows
    const __half* bsrc = Bt + (size_t)(bx * 128 + r) * K + p * 16;    // tid<256
    uint32_t a_s = s2u(hsm) + (r * GAP + p * 16) * 2;
    uint32_t b_s = s2u(hsm) + (GA_HALFS + r * GAP + p * 16) * 2;

    // ldmatrix lane offsets (bytes, relative to stage base)
    uint32_t offA[2], offB[4];
    {
        int arow = (lane & 15), acol = (lane >> 4) << 3;
        #pragma unroll
        for (int mt = 0; mt < 2; mt++)
            offA[mt] = ((wm + mt * 16 + arow) * GAP + acol) * 2;
        int brow = ((lane >> 4) << 3) + (lane & 7);
        int bcol = ((lane >> 3) & 1) << 3;
        #pragma unroll
        for (int ntp = 0; ntp < 4; ntp++)
            offB[ntp] = (uint32_t)(GA_HALFS + (wn + ntp * 16 + brow) * GAP + bcol) * 2;
    }

    float acc[2][8][4];
    #pragma unroll
    for (int mt = 0; mt < 2; mt++)
        #pragma unroll
        for (int nt = 0; nt < 8; nt++)
            #pragma unroll
            for (int i = 0; i < 4; i++) acc[mt][nt][i] = 0.f;

    #define GLOAD(ch, st) do {                                  \
        uint32_t ao = a_s + (st) * GSTG_B;                      \
        const __half* ap = asrc + (ch) * 32;                    \
        cp16(ao,      ap);     cp16(ao + 16, ap + 8);           \
        if (tid < 256) {                                        \
            uint32_t bo = b_s + (st) * GSTG_B;                  \
            const __half* bp = bsrc + (ch) * 32;                \
            cp16(bo,      bp); cp16(bo + 16, bp + 8);           \
        }                                                       \
        cp_commit();                                            \
    } while (0)

    GLOAD(0, 0);
    GLOAD(1, 1);

    for (int it = 0; it < 24; it++) {
        if (it < 23) asm volatile("cp.async.wait_group 1;" ::: "memory");
        else         asm volatile("cp.async.wait_group 0;" ::: "memory");
        __syncthreads();   // single barrier per iteration

        if (it + 2 < 24) {
            int st2 = (it + 2) % 3;
            GLOAD(it + 2, st2);
        }

        uint32_t sb = s2u(hsm) + (it % 3) * GSTG_B;

        #pragma unroll
        for (int ks = 0; ks < 2; ks++) {
            uint32_t kadd = ks * 32;   // 16 halves
            uint32_t af[2][4], bf[8][2];
            #pragma unroll
            for (int mt = 0; mt < 2; mt++)
                ldsm4(af[mt], sb + offA[mt] + kadd);
            #pragma unroll
            for (int ntp = 0; ntp < 4; ntp++) {
                uint32_t t[4];
                ldsm4(t, sb + offB[ntp] + kadd);
                bf[2*ntp][0] = t[0]; bf[2*ntp][1] = t[1];
                bf[2*ntp+1][0] = t[2]; bf[2*ntp+1][1] = t[3];
            }
            #pragma unroll
            for (int mt = 0; mt < 2; mt++)
                #pragma unroll
                for (int nt = 0; nt < 8; nt++)
                    mma16(acc[mt][nt], af[mt], bf[nt]);
        }
    }

    // Epilogue
    #pragma unroll
    for (int mt = 0; mt < 2; mt++) {
        #pragma unroll
        for (int rp = 0; rp < 2; rp++) {
            int m = by * 256 + wm + mt * 16 + lg + rp * 8;
            if (QKV) {
                int bb = m >> 11;
                int ss = m & (S_ - 1);
                #pragma unroll
                for (int nt = 0; nt < 8; nt++) {
                    int n = bx * 128 + wn + nt * 8 + 2 * lq;
                    int which = n / D_;
                    int rem = n - which * D_;
                    int hh = rem >> 6, dd = rem & 63;
                    float vx = acc[mt][nt][rp*2 + 0] + bias[n];
                    float vy = acc[mt][nt][rp*2 + 1] + bias[n + 1];
                    if (which == 2) {
                        size_t vi = ((size_t)(bb * H_ + hh) * HD_ + dd) * S_ + ss;
                        g_v[vi]      = __float2half_rn(vx);
                        g_v[vi + S_] = __float2half_rn(vy);
                    } else {
                        __half* dst = (which == 0) ? g_q : g_k;
                        size_t idx = (((size_t)(bb * H_ + hh) * S_ + ss) << 6) + dd;
                        *(__half2*)&dst[idx] = __floats2half2_rn(vx, vy);
                    }
                }
            } else {
                #pragma unroll
                for (int nt = 0; nt < 8; nt++) {
                    int n = bx * 128 + wn + nt * 8 + 2 * lq;
                    float2 v;
                    v.x = acc[mt][nt][rp*2 + 0] + bias[n];
                    v.y = acc[mt][nt][rp*2 + 1] + bias[n + 1];
                    *(float2*)&C[(size_t)m * D_ + n] = v;
                }
            }
        }
    }
}

// ---------------------------------------------------------------------------
// Flash attention (R12 best, unchanged), causal, all-fp16 mma, ldmatrix K/V,
// register P, 2-stage double-buffered K/V, one sync per k-tile.
// One block = (b, h, 128-row q tile); 256 threads (8 warps, 16 rows each).
// ---------------------------------------------------------------------------
#define KSP 72
#define ATILE (64*KSP)
#define ASTG_B (2*ATILE*2)   // K+V per stage, bytes

__global__ __launch_bounds__(256) void flash_attn_h()
{
    extern __shared__ __half hsm[];

    int bid = blockIdx.x;
    int t  = 15 - (bid & 15);          // heavy q-tiles first
    int h  = (bid >> 4) % H_;
    int b  = bid / (16 * H_);
    int tid = threadIdx.x;
    int lane = tid & 31, w = tid >> 5, lg = lane >> 2, lq = lane & 3;
    int q0 = t * 128;
    int diag = 2 * t + (w >> 2);
    int nkt  = 2 * t + 2;

    const __half* Qg = g_q + (size_t)(b * H_ + h) * S_ * HD_;
    const __half* Kg = g_k + (size_t)(b * H_ + h) * S_ * HD_;
    const __half* Vg = g_v + (size_t)(b * H_ + h) * HD_ * S_;   // [d][s]

    int r_ = tid >> 2, seg = tid & 3;
    uint32_t ks_u = s2u(hsm) + (r_ * KSP + seg * 16) * 2;
    uint32_t vs_u = ks_u + ATILE * 2;
    const __half* kg_row = Kg + (size_t)r_ * 64 + seg * 16;
    const __half* vg_row = Vg + (size_t)r_ * S_ + seg * 16;

    uint32_t offK[4], offV[4];
    {
        int brow = ((lane >> 4) << 3) + (lane & 7);
        int bcol = ((lane >> 3) & 1) << 3;
        #pragma unroll
        for (int ntp = 0; ntp < 4; ntp++) {
            offK[ntp] = s2u(hsm) + ((ntp * 16 + brow) * KSP + bcol) * 2;
            offV[ntp] = offK[ntp] + ATILE * 2;
        }
    }

    #define APRE(kt, st) do {                                        \
        uint32_t so = (st) * ASTG_B;                                 \
        const __half* kp = kg_row + (size_t)(kt) * 64 * 64;          \
        const __half* vp = vg_row + (size_t)(kt) * 64;               \
        cp16(ks_u + so,      kp);   cp16(ks_u + so + 16, kp + 8);    \
        cp16(vs_u + so,      vp);   cp16(vs_u + so + 16, vp + 8);    \
        cp_commit();                                                 \
    } while (0)

    APRE(0, 0);
    const __half2 sc2 = __floats2half2_rn(0.125f, 0.125f);
    uint32_t qf[4][4];
    {
        const __half* qr0 = Qg + (size_t)(q0 + w*16 + lg    ) * 64;
        const __half* qr1 = Qg + (size_t)(q0 + w*16 + lg + 8) * 64;
        #pragma unroll
        for (int ks = 0; ks < 4; ks++) {
            int kc = ks * 16 + 2 * lq;
            __half2 h0 = __hmul2(*(const __half2*)(qr0 + kc),     sc2);
            __half2 h1 = __hmul2(*(const __half2*)(qr1 + kc),     sc2);
            __half2 h2 = __hmul2(*(const __half2*)(qr0 + kc + 8), sc2);
            __half2 h3 = __hmul2(*(const __half2*)(qr1 + kc + 8), sc2);
            qf[ks][0] = h2bits(h0); qf[ks][1] = h2bits(h1);
            qf[ks][2] = h2bits(h2); qf[ks][3] = h2bits(h3);
        }
    }

    float mrow[2] = {-INFINITY, -INFINITY};
    float lrow[2] = {0.f, 0.f};
    float o[8][4];
    #pragma unroll
    for (int nt = 0; nt < 8; nt++)
        #pragma unroll
        for (int i = 0; i < 4; i++) o[nt][i] = 0.f;

    for (int kt = 0; kt < nkt; kt++) {
        int st = kt & 1;
        asm volatile("cp.async.wait_group 0;" ::: "memory");
        __syncthreads();

        if (kt + 1 < nkt)
            APRE(kt + 1, st ^ 1);

        if (kt > diag) continue;

        uint32_t so = st * ASTG_B;

        float s[8][4];
        #pragma unroll
        for (int nt = 0; nt < 8; nt++)
            #pragma unroll
            for (int i = 0; i < 4; i++) s[nt][i] = 0.f;

        #pragma unroll
        for (int ks = 0; ks < 4; ks++) {
            uint32_t kadd = so + ks * 32;
            uint32_t bv[8][2];
            #pragma unroll
            for (int ntp = 0; ntp < 4; ntp++) {
                uint32_t tt[4];
                ldsm4(tt, offK[ntp] + kadd);
                bv[2*ntp][0] = tt[0]; bv[2*ntp][1] = tt[1];
                bv[2*ntp+1][0] = tt[2]; bv[2*ntp+1][1] = tt[3];
            }
            #pragma unroll
            for (int nt = 0; nt < 8; nt++)
                mma16(s[nt], qf[ks], bv[nt]);
        }

        if (kt == diag) {
            #pragma unroll
            for (int nt = 0; nt < 8; nt++)
                #pragma unroll
                for (int rp = 0; rp < 2; rp++)
                    #pragma unroll
                    for (int j = 0; j < 2; j++) {
                        int col = nt*8 + 2*lq + j;
                        int row = (w & 3)*16 + lg + rp*8;
                        if (col > row) s[nt][rp*2 + j] = -INFINITY;
                    }
        }

        #pragma unroll
        for (int rp = 0; rp < 2; rp++) {
            float mt = -INFINITY;
            #pragma unroll
            for (int nt = 0; nt < 8; nt++)
                mt = fmaxf(mt, fmaxf(s[nt][rp*2], s[nt][rp*2 + 1]));
            mt = fmaxf(mt, __shfl_xor_sync(0xffffffffu, mt, 1));
            mt = fmaxf(mt, __shfl_xor_sync(0xffffffffu, mt, 2));
            float mnew = fmaxf(mrow[rp], mt);
            float alpha = __expf(mrow[rp] - mnew);
            float rs = 0.f;
            #pragma unroll
            for (int nt = 0; nt < 8; nt++) {
                float e0 = __expf(s[nt][rp*2]     - mnew);
                float e1 = __expf(s[nt][rp*2 + 1] - mnew);
                s[nt][rp*2] = e0; s[nt][rp*2 + 1] = e1;
                rs += e0 + e1;
            }
            rs += __shfl_xor_sync(0xffffffffu, rs, 1);
            rs += __shfl_xor_sync(0xffffffffu, rs, 2);
            lrow[rp] = lrow[rp] * alpha + rs;
            mrow[rp] = mnew;
            #pragma unroll
            for (int nt = 0; nt < 8; nt++) {
                o[nt][rp*2]     *= alpha;
                o[nt][rp*2 + 1] *= alpha;
            }
        }

        #pragma unroll
        for (int ks = 0; ks < 4; ks++) {
            uint32_t pa[4];
            pa[0] = h2bits(__floats2half2_rn(s[2*ks][0],   s[2*ks][1]));
            pa[1] = h2bits(__floats2half2_rn(s[2*ks][2],   s[2*ks][3]));
            pa[2] = h2bits(__floats2half2_rn(s[2*ks+1][0], s[2*ks+1][1]));
            pa[3] = h2bits(__floats2half2_rn(s[2*ks+1][2], s[2*ks+1][3]));
            uint32_t kadd = so + ks * 32;
            uint32_t bv[8][2];
            #pragma unroll
            for (int ntp = 0; ntp < 4; ntp++) {
                uint32_t tt[4];
                ldsm4(tt, offV[ntp] + kadd);
                bv[2*ntp][0] = tt[0]; bv[2*ntp][1] = tt[1];
                bv[2*ntp+1][0] = tt[2]; bv[2*ntp+1][1] = tt[3];
            }
            #pragma unroll
            for (int nt = 0; nt < 8; nt++)
                mma16(o[nt], pa, bv[nt]);
        }
    }

    #pragma unroll
    for (int rp = 0; rp < 2; rp++) {
        float inv = 1.f / lrow[rp];
        int row = q0 + w*16 + lg + rp*8;
        #pragma unroll
        for (int nt = 0; nt < 8; nt++) {
            int d = nt*8 + 2*lq;
            __half2 hv = __floats2half2_rn(o[nt][rp*2] * inv, o[nt][rp*2 + 1] * inv);
            *(__half2*)&g_attn[((size_t)(b * S_ + row)) * D_ + h * 64 + d] = hv;
        }
    }
}

// ---------------------------------------------------------------------------
extern "C" void kernel_launch(void* const* d_in, const int* in_sizes, int n_in,
                              void* d_out, int out_size)
{
    const float* x      = (const float*)d_in[0];
    const float* w_qkv  = (const float*)d_in[1];
    const float* b_qkv  = (const float*)d_in[2];
    const float* w_proj = (const float*)d_in[3];
    const float* b_proj = (const float*)d_in[4];
    float* out = (float*)d_out;

    prep_all<<<2560, 256>>>(x, w_qkv, w_proj);

    int gsmem = 3 * GSTG_B;   // 92160 B (3 stages)
    cudaFuncSetAttribute(gemm_h<true>,
                         cudaFuncAttributeMaxDynamicSharedMemorySize, gsmem);
    cudaFuncSetAttribute(gemm_h<false>,
                         cudaFuncAttributeMaxDynamicSharedMemorySize, gsmem);

    dim3 g1(N3_/128, M_/256);   // (18, 32)
    gemm_h<true><<<g1, 512, gsmem>>>(b_qkv, nullptr);

    int asmem = 2 * ASTG_B;     // 36864 B (2 stages)
    cudaFuncSetAttribute(flash_attn_h,
                         cudaFuncAttributeMaxDynamicSharedMemorySize, asmem);
    flash_attn_h<<<B_ * H_ * (S_/128), 256, asmem>>>();

    dim3 g2(D_/128, M_/256);    // (6, 32)
    gemm_h<false><<<g2, 512, gsmem>>>(b_proj, out);
}

// round 14
// speedup vs baseline: 1.2860x; 1.1486x over previous
#include <cuda_runtime.h>
#include <cuda_fp16.h>
#include <math.h>
#include <stdint.h>

#define B_  4
#define S_  2048
#define D_  768
#define H_  12
#define HD_ 64
#define N3_ (3*D_)
#define M_  (B_*S_)

// Scratch (allocation-free rule: __device__ globals)
__device__ __half g_q[B_*H_*S_*HD_];    // [b,h,s,d] fp16
__device__ __half g_k[B_*H_*S_*HD_];    // [b,h,s,d] fp16
__device__ __half g_v[B_*H_*HD_*S_];    // [b,h,d,s] fp16  (TRANSPOSED)
__device__ __half g_attn[M_*D_];        // [b,s, h*64+d] fp16
__device__ __half g_x[M_*D_];           // fp16 x
__device__ __half g_wq[N3_*D_];         // w_qkv^T  [N3][K] fp16
__device__ __half g_wp[D_*D_];          // w_proj^T [N][K]  fp16

// ---------------------------------------------------------------------------
// helpers
// ---------------------------------------------------------------------------
__device__ __forceinline__ void mma16(float c[4], const uint32_t a[4], const uint32_t b[2]) {
    asm("mma.sync.aligned.m16n8k16.row.col.f32.f16.f16.f32 "
        "{%0,%1,%2,%3},{%4,%5,%6,%7},{%8,%9},{%0,%1,%2,%3};"
        : "+f"(c[0]), "+f"(c[1]), "+f"(c[2]), "+f"(c[3])
        : "r"(a[0]), "r"(a[1]), "r"(a[2]), "r"(a[3]), "r"(b[0]), "r"(b[1]));
}
__device__ __forceinline__ void ldsm4(uint32_t r[4], uint32_t addr) {
    asm volatile("ldmatrix.sync.aligned.m8n8.x4.shared.b16 {%0,%1,%2,%3}, [%4];"
        : "=r"(r[0]), "=r"(r[1]), "=r"(r[2]), "=r"(r[3]) : "r"(addr));
}
__device__ __forceinline__ void cp16(uint32_t sdst, const void* gsrc) {
    asm volatile("cp.async.cg.shared.global [%0], [%1], 16;" :: "r"(sdst), "l"(gsrc));
}
__device__ __forceinline__ void cp_commit() {
    asm volatile("cp.async.commit_group;" ::: "memory");
}
__device__ __forceinline__ uint32_t s2u(const void* p) {
    return (uint32_t)__cvta_generic_to_shared(p);
}
__device__ __forceinline__ uint32_t h2bits(__half2 h) {
    return *reinterpret_cast<uint32_t*>(&h);
}

// ---------------------------------------------------------------------------
// prep (single launch): transpose+round both weights, round x to fp16
// blocks [0,1728): wq ; [1728,2304): wp ; [2304,2560): x
// ---------------------------------------------------------------------------
__global__ void prep_all(const float* __restrict__ x,
                         const float* __restrict__ wq,
                         const float* __restrict__ wp)
{
    int bx = blockIdx.x;
    if (bx < 1728 + 576) {
        __shared__ float t[32][33];
        const float* src; __half* dst; int cols, c0, r0;
        if (bx < 1728) {
            src = wq; dst = g_wq; cols = N3_;
            c0 = (bx % 72) * 32; r0 = (bx / 72) * 32;
        } else {
            int idx = bx - 1728;
            src = wp; dst = g_wp; cols = D_;
            c0 = (idx % 24) * 32; r0 = (idx / 24) * 32;
        }
        int tx = threadIdx.x & 31, ty = threadIdx.x >> 5;   // 32 x 8
        #pragma unroll
        for (int i = ty; i < 32; i += 8)
            t[i][tx] = src[(size_t)(r0 + i) * cols + c0 + tx];
        __syncthreads();
        #pragma unroll
        for (int i = ty; i < 32; i += 8)
            dst[(size_t)(c0 + i) * D_ + r0 + tx] = __float2half_rn(t[tx][i]);
    } else {
        const float4* src = (const float4*)x;
        __half2* dst = (__half2*)g_x;
        int n4 = (M_*D_)/4;
        for (int i = (bx - 2304) * blockDim.x + threadIdx.x; i < n4;
             i += 256 * blockDim.x) {
            float4 v = src[i];
            dst[i*2]   = __floats2half2_rn(v.x, v.y);
            dst[i*2+1] = __floats2half2_rn(v.z, v.w);
        }
    }
}

// ---------------------------------------------------------------------------
// fp16 GEMM, 128x128 CTA (k-tile 32), 512 threads, 16 warps (4x4),
// warp tile 32x32, 3-stage cp.async + ldmatrix, one sync/iter, 2 CTAs/SM.
// C = A[M,768] @ Wt[N,768]^T + bias.
// ---------------------------------------------------------------------------
#define GAP 40
#define GA_HALFS (128*GAP)                // 5120 (per tile)
#define GSTG_HALFS (2*GA_HALFS)           // 10240
#define GSTG_B (GSTG_HALFS*2)             // 20480

template<bool QKV>
__global__ __launch_bounds__(512, 2) void gemm_h(
    const float* __restrict__ bias, float* __restrict__ C)
{
    extern __shared__ __half hsm[];
    const int K = D_;
    int tid = threadIdx.x, bx = blockIdx.x, by = blockIdx.y;
    int lane = tid & 31, wid = tid >> 5, lg = lane >> 2, lq = lane & 3;
    int wm = (wid >> 2) * 32, wn = (wid & 3) * 32;

    const __half* Ab = QKV ? (const __half*)g_x  : (const __half*)g_attn;
    const __half* Bt = QKV ? (const __half*)g_wq : (const __half*)g_wp;

    int r = tid >> 2, c = tid & 3;   // 128 rows, 4 16B-chunks per 32-half row
    const __half* asrc = Ab + (size_t)(by * 128 + r) * K + c * 8;
    const __half* bsrc = Bt + (size_t)(bx * 128 + r) * K + c * 8;
    uint32_t a_s = s2u(hsm) + (r * GAP + c * 8) * 2;
    uint32_t b_s = s2u(hsm) + (GA_HALFS + r * GAP + c * 8) * 2;

    // ldmatrix lane offsets (bytes, relative to stage base)
    uint32_t offA[2], offB[2];
    {
        int arow = (lane & 15), acol = (lane >> 4) << 3;
        #pragma unroll
        for (int mt = 0; mt < 2; mt++)
            offA[mt] = ((wm + mt * 16 + arow) * GAP + acol) * 2;
        int brow = ((lane >> 4) << 3) + (lane & 7);
        int bcol = ((lane >> 3) & 1) << 3;
        #pragma unroll
        for (int ntp = 0; ntp < 2; ntp++)
            offB[ntp] = (uint32_t)(GA_HALFS + (wn + ntp * 16 + brow) * GAP + bcol) * 2;
    }

    float acc[2][4][4];
    #pragma unroll
    for (int mt = 0; mt < 2; mt++)
        #pragma unroll
        for (int nt = 0; nt < 4; nt++)
            #pragma unroll
            for (int i = 0; i < 4; i++) acc[mt][nt][i] = 0.f;

    #define GLOAD(ch, st) do {                                  \
        cp16(a_s + (st) * GSTG_B, asrc + (ch) * 32);            \
        cp16(b_s + (st) * GSTG_B, bsrc + (ch) * 32);            \
        cp_commit();                                            \
    } while (0)

    GLOAD(0, 0);
    GLOAD(1, 1);

    for (int it = 0; it < 24; it++) {
        if (it < 23) asm volatile("cp.async.wait_group 1;" ::: "memory");
        else         asm volatile("cp.async.wait_group 0;" ::: "memory");
        __syncthreads();   // single barrier per iteration

        if (it + 2 < 24) {
            int st2 = (it + 2) % 3;
            GLOAD(it + 2, st2);
        }

        uint32_t sb = s2u(hsm) + (it % 3) * GSTG_B;

        #pragma unroll
        for (int ks = 0; ks < 2; ks++) {
            uint32_t kadd = ks * 32;   // 16 halves
            uint32_t af[2][4], bf[4][2];
            #pragma unroll
            for (int mt = 0; mt < 2; mt++)
                ldsm4(af[mt], sb + offA[mt] + kadd);
            #pragma unroll
            for (int ntp = 0; ntp < 2; ntp++) {
                uint32_t t[4];
                ldsm4(t, sb + offB[ntp] + kadd);
                bf[2*ntp][0] = t[0]; bf[2*ntp][1] = t[1];
                bf[2*ntp+1][0] = t[2]; bf[2*ntp+1][1] = t[3];
            }
            #pragma unroll
            for (int mt = 0; mt < 2; mt++)
                #pragma unroll
                for (int nt = 0; nt < 4; nt++)
                    mma16(acc[mt][nt], af[mt], bf[nt]);
        }
    }

    // Epilogue
    #pragma unroll
    for (int mt = 0; mt < 2; mt++) {
        #pragma unroll
        for (int rp = 0; rp < 2; rp++) {
            int m = by * 128 + wm + mt * 16 + lg + rp * 8;
            if (QKV) {
                int bb = m >> 11;
                int ss = m & (S_ - 1);
                #pragma unroll
                for (int nt = 0; nt < 4; nt++) {
                    int n = bx * 128 + wn + nt * 8 + 2 * lq;
                    int which = n / D_;
                    int rem = n - which * D_;
                    int hh = rem >> 6, dd = rem & 63;
                    float vx = acc[mt][nt][rp*2 + 0] + bias[n];
                    float vy = acc[mt][nt][rp*2 + 1] + bias[n + 1];
                    if (which == 2) {
                        size_t vi = ((size_t)(bb * H_ + hh) * HD_ + dd) * S_ + ss;
                        g_v[vi]      = __float2half_rn(vx);
                        g_v[vi + S_] = __float2half_rn(vy);
                    } else {
                        __half* dst = (which == 0) ? g_q : g_k;
                        size_t idx = (((size_t)(bb * H_ + hh) * S_ + ss) << 6) + dd;
                        *(__half2*)&dst[idx] = __floats2half2_rn(vx, vy);
                    }
                }
            } else {
                #pragma unroll
                for (int nt = 0; nt < 4; nt++) {
                    int n = bx * 128 + wn + nt * 8 + 2 * lq;
                    float2 v;
                    v.x = acc[mt][nt][rp*2 + 0] + bias[n];
                    v.y = acc[mt][nt][rp*2 + 1] + bias[n + 1];
                    *(float2*)&C[(size_t)m * D_ + n] = v;
                }
            }
        }
    }
}

// ---------------------------------------------------------------------------
// Flash attention (R12 best, unchanged), causal, all-fp16 mma, ldmatrix K/V,
// register P, 2-stage double-buffered K/V, one sync per k-tile.
// One block = (b, h, 128-row q tile); 256 threads (8 warps, 16 rows each).
// ---------------------------------------------------------------------------
#define KSP 72
#define ATILE (64*KSP)
#define ASTG_B (2*ATILE*2)   // K+V per stage, bytes

__global__ __launch_bounds__(256) void flash_attn_h()
{
    extern __shared__ __half hsm[];

    int bid = blockIdx.x;
    int t  = 15 - (bid & 15);          // heavy q-tiles first
    int h  = (bid >> 4) % H_;
    int b  = bid / (16 * H_);
    int tid = threadIdx.x;
    int lane = tid & 31, w = tid >> 5, lg = lane >> 2, lq = lane & 3;
    int q0 = t * 128;
    int diag = 2 * t + (w >> 2);
    int nkt  = 2 * t + 2;

    const __half* Qg = g_q + (size_t)(b * H_ + h) * S_ * HD_;
    const __half* Kg = g_k + (size_t)(b * H_ + h) * S_ * HD_;
    const __half* Vg = g_v + (size_t)(b * H_ + h) * HD_ * S_;   // [d][s]

    int r_ = tid >> 2, seg = tid & 3;
    uint32_t ks_u = s2u(hsm) + (r_ * KSP + seg * 16) * 2;
    uint32_t vs_u = ks_u + ATILE * 2;
    const __half* kg_row = Kg + (size_t)r_ * 64 + seg * 16;
    const __half* vg_row = Vg + (size_t)r_ * S_ + seg * 16;

    uint32_t offK[4], offV[4];
    {
        int brow = ((lane >> 4) << 3) + (lane & 7);
        int bcol = ((lane >> 3) & 1) << 3;
        #pragma unroll
        for (int ntp = 0; ntp < 4; ntp++) {
            offK[ntp] = s2u(hsm) + ((ntp * 16 + brow) * KSP + bcol) * 2;
            offV[ntp] = offK[ntp] + ATILE * 2;
        }
    }

    #define APRE(kt, st) do {                                        \
        uint32_t so = (st) * ASTG_B;                                 \
        const __half* kp = kg_row + (size_t)(kt) * 64 * 64;          \
        const __half* vp = vg_row + (size_t)(kt) * 64;               \
        cp16(ks_u + so,      kp);   cp16(ks_u + so + 16, kp + 8);    \
        cp16(vs_u + so,      vp);   cp16(vs_u + so + 16, vp + 8);    \
        cp_commit();                                                 \
    } while (0)

    APRE(0, 0);
    const __half2 sc2 = __floats2half2_rn(0.125f, 0.125f);
    uint32_t qf[4][4];
    {
        const __half* qr0 = Qg + (size_t)(q0 + w*16 + lg    ) * 64;
        const __half* qr1 = Qg + (size_t)(q0 + w*16 + lg + 8) * 64;
        #pragma unroll
        for (int ks = 0; ks < 4; ks++) {
            int kc = ks * 16 + 2 * lq;
            __half2 h0 = __hmul2(*(const __half2*)(qr0 + kc),     sc2);
            __half2 h1 = __hmul2(*(const __half2*)(qr1 + kc),     sc2);
            __half2 h2 = __hmul2(*(const __half2*)(qr0 + kc + 8), sc2);
            __half2 h3 = __hmul2(*(const __half2*)(qr1 + kc + 8), sc2);
            qf[ks][0] = h2bits(h0); qf[ks][1] = h2bits(h1);
            qf[ks][2] = h2bits(h2); qf[ks][3] = h2bits(h3);
        }
    }

    float mrow[2] = {-INFINITY, -INFINITY};
    float lrow[2] = {0.f, 0.f};
    float o[8][4];
    #pragma unroll
    for (int nt = 0; nt < 8; nt++)
        #pragma unroll
        for (int i = 0; i < 4; i++) o[nt][i] = 0.f;

    for (int kt = 0; kt < nkt; kt++) {
        int st = kt & 1;
        asm volatile("cp.async.wait_group 0;" ::: "memory");
        __syncthreads();

        if (kt + 1 < nkt)
            APRE(kt + 1, st ^ 1);

        if (kt > diag) continue;

        uint32_t so = st * ASTG_B;

        float s[8][4];
        #pragma unroll
        for (int nt = 0; nt < 8; nt++)
            #pragma unroll
            for (int i = 0; i < 4; i++) s[nt][i] = 0.f;

        #pragma unroll
        for (int ks = 0; ks < 4; ks++) {
            uint32_t kadd = so + ks * 32;
            uint32_t bv[8][2];
            #pragma unroll
            for (int ntp = 0; ntp < 4; ntp++) {
                uint32_t tt[4];
                ldsm4(tt, offK[ntp] + kadd);
                bv[2*ntp][0] = tt[0]; bv[2*ntp][1] = tt[1];
                bv[2*ntp+1][0] = tt[2]; bv[2*ntp+1][1] = tt[3];
            }
            #pragma unroll
            for (int nt = 0; nt < 8; nt++)
                mma16(s[nt], qf[ks], bv[nt]);
        }

        if (kt == diag) {
            #pragma unroll
            for (int nt = 0; nt < 8; nt++)
                #pragma unroll
                for (int rp = 0; rp < 2; rp++)
                    #pragma unroll
                    for (int j = 0; j < 2; j++) {
                        int col = nt*8 + 2*lq + j;
                        int row = (w & 3)*16 + lg + rp*8;
                        if (col > row) s[nt][rp*2 + j] = -INFINITY;
                    }
        }

        #pragma unroll
        for (int rp = 0; rp < 2; rp++) {
            float mt = -INFINITY;
            #pragma unroll
            for (int nt = 0; nt < 8; nt++)
                mt = fmaxf(mt, fmaxf(s[nt][rp*2], s[nt][rp*2 + 1]));
            mt = fmaxf(mt, __shfl_xor_sync(0xffffffffu, mt, 1));
            mt = fmaxf(mt, __shfl_xor_sync(0xffffffffu, mt, 2));
            float mnew = fmaxf(mrow[rp], mt);
            float alpha = __expf(mrow[rp] - mnew);
            float rs = 0.f;
            #pragma unroll
            for (int nt = 0; nt < 8; nt++) {
                float e0 = __expf(s[nt][rp*2]     - mnew);
                float e1 = __expf(s[nt][rp*2 + 1] - mnew);
                s[nt][rp*2] = e0; s[nt][rp*2 + 1] = e1;
                rs += e0 + e1;
            }
            rs += __shfl_xor_sync(0xffffffffu, rs, 1);
            rs += __shfl_xor_sync(0xffffffffu, rs, 2);
            lrow[rp] = lrow[rp] * alpha + rs;
            mrow[rp] = mnew;
            #pragma unroll
            for (int nt = 0; nt < 8; nt++) {
                o[nt][rp*2]     *= alpha;
                o[nt][rp*2 + 1] *= alpha;
            }
        }

        #pragma unroll
        for (int ks = 0; ks < 4; ks++) {
            uint32_t pa[4];
            pa[0] = h2bits(__floats2half2_rn(s[2*ks][0],   s[2*ks][1]));
            pa[1] = h2bits(__floats2half2_rn(s[2*ks][2],   s[2*ks][3]));
            pa[2] = h2bits(__floats2half2_rn(s[2*ks+1][0], s[2*ks+1][1]));
            pa[3] = h2bits(__floats2half2_rn(s[2*ks+1][2], s[2*ks+1][3]));
            uint32_t kadd = so + ks * 32;
            uint32_t bv[8][2];
            #pragma unroll
            for (int ntp = 0; ntp < 4; ntp++) {
                uint32_t tt[4];
                ldsm4(tt, offV[ntp] + kadd);
                bv[2*ntp][0] = tt[0]; bv[2*ntp][1] = tt[1];
                bv[2*ntp+1][0] = tt[2]; bv[2*ntp+1][1] = tt[3];
            }
            #pragma unroll
            for (int nt = 0; nt < 8; nt++)
                mma16(o[nt], pa, bv[nt]);
        }
    }

    #pragma unroll
    for (int rp = 0; rp < 2; rp++) {
        float inv = 1.f / lrow[rp];
        int row = q0 + w*16 + lg + rp*8;
        #pragma unroll
        for (int nt = 0; nt < 8; nt++) {
            int d = nt*8 + 2*lq;
            __half2 hv = __floats2half2_rn(o[nt][rp*2] * inv, o[nt][rp*2 + 1] * inv);
            *(__half2*)&g_attn[((size_t)(b * S_ + row)) * D_ + h * 64 + d] = hv;
        }
    }
}

// ---------------------------------------------------------------------------
extern "C" void kernel_launch(void* const* d_in, const int* in_sizes, int n_in,
                              void* d_out, int out_size)
{
    const float* x      = (const float*)d_in[0];
    const float* w_qkv  = (const float*)d_in[1];
    const float* b_qkv  = (const float*)d_in[2];
    const float* w_proj = (const float*)d_in[3];
    const float* b_proj = (const float*)d_in[4];
    float* out = (float*)d_out;

    prep_all<<<2560, 256>>>(x, w_qkv, w_proj);

    int gsmem = 3 * GSTG_B;   // 61440 B (3 stages)
    cudaFuncSetAttribute(gemm_h<true>,
                         cudaFuncAttributeMaxDynamicSharedMemorySize, gsmem);
    cudaFuncSetAttribute(gemm_h<false>,
                         cudaFuncAttributeMaxDynamicSharedMemorySize, gsmem);

    dim3 g1(N3_/128, M_/128);   // (18, 64)
    gemm_h<true><<<g1, 512, gsmem>>>(b_qkv, nullptr);

    int asmem = 2 * ASTG_B;     // 36864 B (2 stages)
    cudaFuncSetAttribute(flash_attn_h,
                         cudaFuncAttributeMaxDynamicSharedMemorySize, asmem);
    flash_attn_h<<<B_ * H_ * (S_/128), 256, asmem>>>();

    dim3 g2(D_/128, M_/128);    // (6, 64)
    gemm_h<false><<<g2, 512, gsmem>>>(b_proj, out);
}

// round 15
// speedup vs baseline: 1.3402x; 1.0421x over previous
#include <cuda_runtime.h>
#include <cuda_fp16.h>
#include <math.h>
#include <stdint.h>

#define B_  4
#define S_  2048
#define D_  768
#define H_  12
#define HD_ 64
#define N3_ (3*D_)
#define M_  (B_*S_)

// Scratch (allocation-free rule: __device__ globals)
__device__ __half g_q[B_*H_*S_*HD_];    // [b,h,s,d] fp16
__device__ __half g_k[B_*H_*S_*HD_];    // [b,h,s,d] fp16
__device__ __half g_v[B_*H_*HD_*S_];    // [b,h,d,s] fp16  (TRANSPOSED)
__device__ __half g_attn[M_*D_];        // [b,s, h*64+d] fp16
__device__ __half g_x[M_*D_];           // fp16 x
__device__ __half g_wq[N3_*D_];         // w_qkv^T  [N3][K] fp16
__device__ __half g_wp[D_*D_];          // w_proj^T [N][K]  fp16

// ---------------------------------------------------------------------------
// helpers
// ---------------------------------------------------------------------------
__device__ __forceinline__ void mma16(float c[4], const uint32_t a[4], const uint32_t b[2]) {
    asm("mma.sync.aligned.m16n8k16.row.col.f32.f16.f16.f32 "
        "{%0,%1,%2,%3},{%4,%5,%6,%7},{%8,%9},{%0,%1,%2,%3};"
        : "+f"(c[0]), "+f"(c[1]), "+f"(c[2]), "+f"(c[3])
        : "r"(a[0]), "r"(a[1]), "r"(a[2]), "r"(a[3]), "r"(b[0]), "r"(b[1]));
}
__device__ __forceinline__ void ldsm4(uint32_t r[4], uint32_t addr) {
    asm volatile("ldmatrix.sync.aligned.m8n8.x4.shared.b16 {%0,%1,%2,%3}, [%4];"
        : "=r"(r[0]), "=r"(r[1]), "=r"(r[2]), "=r"(r[3]) : "r"(addr));
}
__device__ __forceinline__ void cp16(uint32_t sdst, const void* gsrc) {
    asm volatile("cp.async.cg.shared.global [%0], [%1], 16;" :: "r"(sdst), "l"(gsrc));
}
__device__ __forceinline__ void cp_commit() {
    asm volatile("cp.async.commit_group;" ::: "memory");
}
__device__ __forceinline__ uint32_t s2u(const void* p) {
    return (uint32_t)__cvta_generic_to_shared(p);
}
__device__ __forceinline__ uint32_t h2bits(__half2 h) {
    return *reinterpret_cast<uint32_t*>(&h);
}
__device__ __forceinline__ float ex2(float x) {
    float r;
    asm("ex2.approx.ftz.f32 %0, %1;" : "=f"(r) : "f"(x));
    return r;
}

// ---------------------------------------------------------------------------
// prep (single launch): transpose+round both weights, round x to fp16
// blocks [0,1728): wq ; [1728,2304): wp ; [2304,2560): x
// ---------------------------------------------------------------------------
__global__ void prep_all(const float* __restrict__ x,
                         const float* __restrict__ wq,
                         const float* __restrict__ wp)
{
    int bx = blockIdx.x;
    if (bx < 1728 + 576) {
        __shared__ float t[32][33];
        const float* src; __half* dst; int cols, c0, r0;
        if (bx < 1728) {
            src = wq; dst = g_wq; cols = N3_;
            c0 = (bx % 72) * 32; r0 = (bx / 72) * 32;
        } else {
            int idx = bx - 1728;
            src = wp; dst = g_wp; cols = D_;
            c0 = (idx % 24) * 32; r0 = (idx / 24) * 32;
        }
        int tx = threadIdx.x & 31, ty = threadIdx.x >> 5;   // 32 x 8
        #pragma unroll
        for (int i = ty; i < 32; i += 8)
            t[i][tx] = src[(size_t)(r0 + i) * cols + c0 + tx];
        __syncthreads();
        #pragma unroll
        for (int i = ty; i < 32; i += 8)
            dst[(size_t)(c0 + i) * D_ + r0 + tx] = __float2half_rn(t[tx][i]);
    } else {
        const float4* src = (const float4*)x;
        __half2* dst = (__half2*)g_x;
        int n4 = (M_*D_)/4;
        for (int i = (bx - 2304) * blockDim.x + threadIdx.x; i < n4;
             i += 256 * blockDim.x) {
            float4 v = src[i];
            dst[i*2]   = __floats2half2_rn(v.x, v.y);
            dst[i*2+1] = __floats2half2_rn(v.z, v.w);
        }
    }
}

// ---------------------------------------------------------------------------
// fp16 GEMM (R14 best, unchanged): 128x128 CTA, 512 threads, 16 warps (4x4),
// warp tile 32x32, 3-stage cp.async + ldmatrix, one sync/iter, 2 CTAs/SM.
// ---------------------------------------------------------------------------
#define GAP 40
#define GA_HALFS (128*GAP)
#define GSTG_HALFS (2*GA_HALFS)
#define GSTG_B (GSTG_HALFS*2)

template<bool QKV>
__global__ __launch_bounds__(512, 2) void gemm_h(
    const float* __restrict__ bias, float* __restrict__ C)
{
    extern __shared__ __half hsm[];
    const int K = D_;
    int tid = threadIdx.x, bx = blockIdx.x, by = blockIdx.y;
    int lane = tid & 31, wid = tid >> 5, lg = lane >> 2, lq = lane & 3;
    int wm = (wid >> 2) * 32, wn = (wid & 3) * 32;

    const __half* Ab = QKV ? (const __half*)g_x  : (const __half*)g_attn;
    const __half* Bt = QKV ? (const __half*)g_wq : (const __half*)g_wp;

    int r = tid >> 2, c = tid & 3;
    const __half* asrc = Ab + (size_t)(by * 128 + r) * K + c * 8;
    const __half* bsrc = Bt + (size_t)(bx * 128 + r) * K + c * 8;
    uint32_t a_s = s2u(hsm) + (r * GAP + c * 8) * 2;
    uint32_t b_s = s2u(hsm) + (GA_HALFS + r * GAP + c * 8) * 2;

    uint32_t offA[2], offB[2];
    {
        int arow = (lane & 15), acol = (lane >> 4) << 3;
        #pragma unroll
        for (int mt = 0; mt < 2; mt++)
            offA[mt] = ((wm + mt * 16 + arow) * GAP + acol) * 2;
        int brow = ((lane >> 4) << 3) + (lane & 7);
        int bcol = ((lane >> 3) & 1) << 3;
        #pragma unroll
        for (int ntp = 0; ntp < 2; ntp++)
            offB[ntp] = (uint32_t)(GA_HALFS + (wn + ntp * 16 + brow) * GAP + bcol) * 2;
    }

    float acc[2][4][4];
    #pragma unroll
    for (int mt = 0; mt < 2; mt++)
        #pragma unroll
        for (int nt = 0; nt < 4; nt++)
            #pragma unroll
            for (int i = 0; i < 4; i++) acc[mt][nt][i] = 0.f;

    #define GLOAD(ch, st) do {                                  \
        cp16(a_s + (st) * GSTG_B, asrc + (ch) * 32);            \
        cp16(b_s + (st) * GSTG_B, bsrc + (ch) * 32);            \
        cp_commit();                                            \
    } while (0)

    GLOAD(0, 0);
    GLOAD(1, 1);

    for (int it = 0; it < 24; it++) {
        if (it < 23) asm volatile("cp.async.wait_group 1;" ::: "memory");
        else         asm volatile("cp.async.wait_group 0;" ::: "memory");
        __syncthreads();

        if (it + 2 < 24) {
            int st2 = (it + 2) % 3;
            GLOAD(it + 2, st2);
        }

        uint32_t sb = s2u(hsm) + (it % 3) * GSTG_B;

        #pragma unroll
        for (int ks = 0; ks < 2; ks++) {
            uint32_t kadd = ks * 32;
            uint32_t af[2][4], bf[4][2];
            #pragma unroll
            for (int mt = 0; mt < 2; mt++)
                ldsm4(af[mt], sb + offA[mt] + kadd);
            #pragma unroll
            for (int ntp = 0; ntp < 2; ntp++) {
                uint32_t t[4];
                ldsm4(t, sb + offB[ntp] + kadd);
                bf[2*ntp][0] = t[0]; bf[2*ntp][1] = t[1];
                bf[2*ntp+1][0] = t[2]; bf[2*ntp+1][1] = t[3];
            }
            #pragma unroll
            for (int mt = 0; mt < 2; mt++)
                #pragma unroll
                for (int nt = 0; nt < 4; nt++)
                    mma16(acc[mt][nt], af[mt], bf[nt]);
        }
    }

    #pragma unroll
    for (int mt = 0; mt < 2; mt++) {
        #pragma unroll
        for (int rp = 0; rp < 2; rp++) {
            int m = by * 128 + wm + mt * 16 + lg + rp * 8;
            if (QKV) {
                int bb = m >> 11;
                int ss = m & (S_ - 1);
                #pragma unroll
                for (int nt = 0; nt < 4; nt++) {
                    int n = bx * 128 + wn + nt * 8 + 2 * lq;
                    int which = n / D_;
                    int rem = n - which * D_;
                    int hh = rem >> 6, dd = rem & 63;
                    float vx = acc[mt][nt][rp*2 + 0] + bias[n];
                    float vy = acc[mt][nt][rp*2 + 1] + bias[n + 1];
                    if (which == 2) {
                        size_t vi = ((size_t)(bb * H_ + hh) * HD_ + dd) * S_ + ss;
                        g_v[vi]      = __float2half_rn(vx);
                        g_v[vi + S_] = __float2half_rn(vy);
                    } else {
                        __half* dst = (which == 0) ? g_q : g_k;
                        size_t idx = (((size_t)(bb * H_ + hh) * S_ + ss) << 6) + dd;
                        *(__half2*)&dst[idx] = __floats2half2_rn(vx, vy);
                    }
                }
            } else {
                #pragma unroll
                for (int nt = 0; nt < 4; nt++) {
                    int n = bx * 128 + wn + nt * 8 + 2 * lq;
                    float2 v;
                    v.x = acc[mt][nt][rp*2 + 0] + bias[n];
                    v.y = acc[mt][nt][rp*2 + 1] + bias[n + 1];
                    *(float2*)&C[(size_t)m * D_ + n] = v;
                }
            }
        }
    }
}

// ---------------------------------------------------------------------------
// Flash attention, causal, all-fp16 mma, ldmatrix K/V, register P,
// 2-stage double-buffered K/V, base-2 softmax (log2e folded into Q scale),
// 2 CTAs/SM via launch bounds. One block = (b, h, 128-row q tile), 256 thr.
// ---------------------------------------------------------------------------
#define KSP 72
#define ATILE (64*KSP)
#define ASTG_B (2*ATILE*2)   // K+V per stage, bytes

__global__ __launch_bounds__(256, 2) void flash_attn_h()
{
    extern __shared__ __half hsm[];

    int bid = blockIdx.x;
    int t  = 15 - (bid & 15);          // heavy q-tiles first
    int h  = (bid >> 4) % H_;
    int b  = bid / (16 * H_);
    int tid = threadIdx.x;
    int lane = tid & 31, w = tid >> 5, lg = lane >> 2, lq = lane & 3;
    int q0 = t * 128;
    int diag = 2 * t + (w >> 2);
    int nkt  = 2 * t + 2;

    const __half* Qg = g_q + (size_t)(b * H_ + h) * S_ * HD_;
    const __half* Kg = g_k + (size_t)(b * H_ + h) * S_ * HD_;
    const __half* Vg = g_v + (size_t)(b * H_ + h) * HD_ * S_;   // [d][s]

    int r_ = tid >> 2, seg = tid & 3;
    uint32_t ks_u = s2u(hsm) + (r_ * KSP + seg * 16) * 2;
    uint32_t vs_u = ks_u + ATILE * 2;
    const __half* kg_row = Kg + (size_t)r_ * 64 + seg * 16;
    const __half* vg_row = Vg + (size_t)r_ * S_ + seg * 16;

    uint32_t offK[4], offV[4];
    {
        int brow = ((lane >> 4) << 3) + (lane & 7);
        int bcol = ((lane >> 3) & 1) << 3;
        #pragma unroll
        for (int ntp = 0; ntp < 4; ntp++) {
            offK[ntp] = s2u(hsm) + ((ntp * 16 + brow) * KSP + bcol) * 2;
            offV[ntp] = offK[ntp] + ATILE * 2;
        }
    }

    #define APRE(kt, st) do {                                        \
        uint32_t so = (st) * ASTG_B;                                 \
        const __half* kp = kg_row + (size_t)(kt) * 64 * 64;          \
        const __half* vp = vg_row + (size_t)(kt) * 64;               \
        cp16(ks_u + so,      kp);   cp16(ks_u + so + 16, kp + 8);    \
        cp16(vs_u + so,      vp);   cp16(vs_u + so + 16, vp + 8);    \
        cp_commit();                                                 \
    } while (0)

    APRE(0, 0);
    // Q scale = (1/8) * log2(e): softmax computed base-2 (single EX2 per prob)
    const __half2 sc2 = __floats2half2_rn(0.125f * 1.44269504f,
                                          0.125f * 1.44269504f);
    uint32_t qf[4][4];
    {
        const __half* qr0 = Qg + (size_t)(q0 + w*16 + lg    ) * 64;
        const __half* qr1 = Qg + (size_t)(q0 + w*16 + lg + 8) * 64;
        #pragma unroll
        for (int ks = 0; ks < 4; ks++) {
            int kc = ks * 16 + 2 * lq;
            __half2 h0 = __hmul2(*(const __half2*)(qr0 + kc),     sc2);
            __half2 h1 = __hmul2(*(const __half2*)(qr1 + kc),     sc2);
            __half2 h2 = __hmul2(*(const __half2*)(qr0 + kc + 8), sc2);
            __half2 h3 = __hmul2(*(const __half2*)(qr1 + kc + 8), sc2);
            qf[ks][0] = h2bits(h0); qf[ks][1] = h2bits(h1);
            qf[ks][2] = h2bits(h2); qf[ks][3] = h2bits(h3);
        }
    }

    float mrow[2] = {-INFINITY, -INFINITY};
    float lrow[2] = {0.f, 0.f};
    float o[8][4];
    #pragma unroll
    for (int nt = 0; nt < 8; nt++)
        #pragma unroll
        for (int i = 0; i < 4; i++) o[nt][i] = 0.f;

    for (int kt = 0; kt < nkt; kt++) {
        int st = kt & 1;
        asm volatile("cp.async.wait_group 0;" ::: "memory");
        __syncthreads();

        if (kt + 1 < nkt)
            APRE(kt + 1, st ^ 1);

        if (kt > diag) continue;

        uint32_t so = st * ASTG_B;

        // S = Q @ K^T (log2-domain scores); interleaved ldsm->mma (low regs)
        float s[8][4];
        #pragma unroll
        for (int nt = 0; nt < 8; nt++)
            #pragma unroll
            for (int i = 0; i < 4; i++) s[nt][i] = 0.f;

        #pragma unroll
        for (int ks = 0; ks < 4; ks++) {
            uint32_t kadd = so + ks * 32;
            #pragma unroll
            for (int ntp = 0; ntp < 4; ntp++) {
                uint32_t tt[4];
                ldsm4(tt, offK[ntp] + kadd);
                mma16(s[2*ntp],     qf[ks], tt);
                mma16(s[2*ntp + 1], qf[ks], tt + 2);
            }
        }

        if (kt == diag) {
            #pragma unroll
            for (int nt = 0; nt < 8; nt++)
                #pragma unroll
                for (int rp = 0; rp < 2; rp++)
                    #pragma unroll
                    for (int j = 0; j < 2; j++) {
                        int col = nt*8 + 2*lq + j;
                        int row = (w & 3)*16 + lg + rp*8;
                        if (col > row) s[nt][rp*2 + j] = -INFINITY;
                    }
        }

        // Online softmax, base-2
        #pragma unroll
        for (int rp = 0; rp < 2; rp++) {
            float mt = -INFINITY;
            #pragma unroll
            for (int nt = 0; nt < 8; nt++)
                mt = fmaxf(mt, fmaxf(s[nt][rp*2], s[nt][rp*2 + 1]));
            mt = fmaxf(mt, __shfl_xor_sync(0xffffffffu, mt, 1));
            mt = fmaxf(mt, __shfl_xor_sync(0xffffffffu, mt, 2));
            float mnew = fmaxf(mrow[rp], mt);
            float alpha = ex2(mrow[rp] - mnew);
            float rs = 0.f;
            #pragma unroll
            for (int nt = 0; nt < 8; nt++) {
                float e0 = ex2(s[nt][rp*2]     - mnew);
                float e1 = ex2(s[nt][rp*2 + 1] - mnew);
                s[nt][rp*2] = e0; s[nt][rp*2 + 1] = e1;
                rs += e0 + e1;
            }
            rs += __shfl_xor_sync(0xffffffffu, rs, 1);
            rs += __shfl_xor_sync(0xffffffffu, rs, 2);
            lrow[rp] = lrow[rp] * alpha + rs;
            mrow[rp] = mnew;
            #pragma unroll
            for (int nt = 0; nt < 8; nt++) {
                o[nt][rp*2]     *= alpha;
                o[nt][rp*2 + 1] *= alpha;
            }
        }

        // O += P @ V (P packed in registers; interleaved ldsm->mma)
        #pragma unroll
        for (int ks = 0; ks < 4; ks++) {
            uint32_t pa[4];
            pa[0] = h2bits(__floats2half2_rn(s[2*ks][0],   s[2*ks][1]));
            pa[1] = h2bits(__floats2half2_rn(s[2*ks][2],   s[2*ks][3]));
            pa[2] = h2bits(__floats2half2_rn(s[2*ks+1][0], s[2*ks+1][1]));
            pa[3] = h2bits(__floats2half2_rn(s[2*ks+1][2], s[2*ks+1][3]));
            uint32_t kadd = so + ks * 32;
            #pragma unroll
            for (int ntp = 0; ntp < 4; ntp++) {
                uint32_t tt[4];
                ldsm4(tt, offV[ntp] + kadd);
                mma16(o[2*ntp],     pa, tt);
                mma16(o[2*ntp + 1], pa, tt + 2);
            }
        }
    }

    // Normalize, fp16-round (proj A operand), write [b, s, h*64+d]
    #pragma unroll
    for (int rp = 0; rp < 2; rp++) {
        float inv = 1.f / lrow[rp];
        int row = q0 + w*16 + lg + rp*8;
        #pragma unroll
        for (int nt = 0; nt < 8; nt++) {
            int d = nt*8 + 2*lq;
            __half2 hv = __floats2half2_rn(o[nt][rp*2] * inv, o[nt][rp*2 + 1] * inv);
            *(__half2*)&g_attn[((size_t)(b * S_ + row)) * D_ + h * 64 + d] = hv;
        }
    }
}

// ---------------------------------------------------------------------------
extern "C" void kernel_launch(void* const* d_in, const int* in_sizes, int n_in,
                              void* d_out, int out_size)
{
    const float* x      = (const float*)d_in[0];
    const float* w_qkv  = (const float*)d_in[1];
    const float* b_qkv  = (const float*)d_in[2];
    const float* w_proj = (const float*)d_in[3];
    const float* b_proj = (const float*)d_in[4];
    float* out = (float*)d_out;

    prep_all<<<2560, 256>>>(x, w_qkv, w_proj);

    int gsmem = 3 * GSTG_B;   // 61440 B
    cudaFuncSetAttribute(gemm_h<true>,
                         cudaFuncAttributeMaxDynamicSharedMemorySize, gsmem);
    cudaFuncSetAttribute(gemm_h<false>,
                         cudaFuncAttributeMaxDynamicSharedMemorySize, gsmem);

    dim3 g1(N3_/128, M_/128);   // (18, 64)
    gemm_h<true><<<g1, 512, gsmem>>>(b_qkv, nullptr);

    int asmem = 2 * ASTG_B;     // 36864 B
    cudaFuncSetAttribute(flash_attn_h,
                         cudaFuncAttributeMaxDynamicSharedMemorySize, asmem);
    flash_attn_h<<<B_ * H_ * (S_/128), 256, asmem>>>();

    dim3 g2(D_/128, M_/128);    // (6, 64)
    gemm_h<false><<<g2, 512, gsmem>>>(b_proj, out);
}